// round 1
// baseline (speedup 1.0000x reference)
#include <cuda_runtime.h>

#define NN 30000
#define EE 480000
#define ET (EE + NN)   // 510000 edges incl. self loops
#define BB 64
#define FIN 128
#define HID 64
#define ED 32
#define C1 256         // 4*HID (layer1 out)
#define NEG 0.2f
#define EPS 1e-5f

// ------------------- scratch (device globals; no allocs allowed) -------------
__device__ float    d_mean_ea[NN * ED];
__device__ float    d_cnt[NN];
__device__ float    d_xs1[NN * C1];
__device__ float    d_als1[NN * 4];
__device__ float    d_ald1[NN * 4];
__device__ float    d_c1[ED * 4];
__device__ float    d_alpha1[(size_t)ET * 4];
__device__ unsigned d_m1[NN * 4];
__device__ float    d_s1[NN * 4];
__device__ float    d_out1[NN * C1];
__device__ float    d_colsum[C1];
__device__ float    d_colsq[C1];
__device__ float    d_xs2[NN * HID];
__device__ float    d_als2[NN];
__device__ float    d_ald2[NN];
__device__ float    d_c2[ED];
__device__ float    d_alpha2[ET];
__device__ unsigned d_m2[NN];
__device__ float    d_s2[NN];
__device__ float    d_out2[NN * HID];
__device__ float    d_gate[NN];
__device__ unsigned d_gm[BB];
__device__ float    d_gs[BB];

// ------------------- helpers -------------------------------------------------
__device__ __forceinline__ unsigned fenc(float f) {
    unsigned u = __float_as_uint(f);
    return (u & 0x80000000u) ? ~u : (u | 0x80000000u);
}
__device__ __forceinline__ float fdec(unsigned u) {
    return (u & 0x80000000u) ? __uint_as_float(u & 0x7FFFFFFFu) : __uint_as_float(~u);
}

__global__ void fill_f(float* p, float v, int n) {
    int i = blockIdx.x * blockDim.x + threadIdx.x;
    if (i < n) p[i] = v;
}
__global__ void fill_u(unsigned* p, unsigned v, int n) {
    int i = blockIdx.x * blockDim.x + threadIdx.x;
    if (i < n) p[i] = v;
}

// ------------------- self-loop mean edge attr --------------------------------
__global__ void ea_mean_accum(const float* __restrict__ ea, const int* __restrict__ dst) {
    int idx = blockIdx.x * blockDim.x + threadIdx.x;
    if (idx >= EE * ED) return;
    int e = idx / ED, d = idx % ED;
    int node = dst[e];
    atomicAdd(&d_mean_ea[node * ED + d], ea[idx]);
    if (d == 0) atomicAdd(&d_cnt[node], 1.0f);
}
__global__ void ea_mean_div() {
    int idx = blockIdx.x * blockDim.x + threadIdx.x;
    if (idx >= NN * ED) return;
    int n = idx / ED;
    float c = d_cnt[n];
    d_mean_ea[idx] /= (c > 1.0f ? c : 1.0f);
}

// ------------------- tiled GEMM C[M,Nc] = A[M,K] x B[K,Nc] ------------------
__global__ void gemm_tiled(const float* __restrict__ A, const float* __restrict__ B,
                           float* __restrict__ C, int M, int K, int Nc) {
    __shared__ float As[16][16];
    __shared__ float Bs[16][17];
    int row = blockIdx.y * 16 + threadIdx.y;
    int col = blockIdx.x * 16 + threadIdx.x;
    float acc = 0.f;
    for (int k0 = 0; k0 < K; k0 += 16) {
        As[threadIdx.y][threadIdx.x] = A[row * K + k0 + threadIdx.x];
        Bs[threadIdx.y][threadIdx.x] = B[(k0 + threadIdx.y) * Nc + col];
        __syncthreads();
#pragma unroll
        for (int k = 0; k < 16; k++) acc += As[threadIdx.y][k] * Bs[k][threadIdx.x];
        __syncthreads();
    }
    C[row * Nc + col] = acc;
}

// ------------------- attention logits ----------------------------------------
// layer1: al_src/al_dst per (n,h), h in [0,4)
__global__ void al_kernel1(const float* __restrict__ as, const float* __restrict__ ad) {
    int idx = blockIdx.x * blockDim.x + threadIdx.x;
    if (idx >= NN * 4) return;
    int n = idx >> 2, h = idx & 3;
    const float* xr = d_xs1 + n * C1 + h * HID;
    float s = 0.f, d = 0.f;
#pragma unroll
    for (int f = 0; f < HID; f++) {
        float v = xr[f];
        s += v * as[h * HID + f];
        d += v * ad[h * HID + f];
    }
    d_als1[idx] = s;
    d_ald1[idx] = d;
}
__global__ void al_kernel2(const float* __restrict__ as, const float* __restrict__ ad) {
    int n = blockIdx.x * blockDim.x + threadIdx.x;
    if (n >= NN) return;
    const float* xr = d_xs2 + n * HID;
    float s = 0.f, d = 0.f;
#pragma unroll
    for (int f = 0; f < HID; f++) {
        float v = xr[f];
        s += v * as[f];
        d += v * ad[f];
    }
    d_als2[n] = s;
    d_ald2[n] = d;
}

// c1[k,h] = sum_f We1[k, h*64+f] * ae1[h*64+f]   (We1 is [32,256])
__global__ void c1_kernel(const float* __restrict__ We1, const float* __restrict__ ae1) {
    int idx = threadIdx.x;   // 128 threads
    if (idx >= ED * 4) return;
    int k = idx >> 2, h = idx & 3;
    float s = 0.f;
#pragma unroll
    for (int f = 0; f < HID; f++) s += We1[k * C1 + h * HID + f] * ae1[h * HID + f];
    d_c1[k * 4 + h] = s;
}
// c2[k] = sum_f We2[k,f] * ae2[f]   (We2 is [32,64])
__global__ void c2_kernel(const float* __restrict__ We2, const float* __restrict__ ae2) {
    int k = threadIdx.x;   // 32 threads
    if (k >= ED) return;
    float s = 0.f;
#pragma unroll
    for (int f = 0; f < HID; f++) s += We2[k * HID + f] * ae2[f];
    d_c2[k] = s;
}

// ------------------- edge alpha + segment max --------------------------------
__global__ void edge_alpha1(const float* __restrict__ ea, const int* __restrict__ src,
                            const int* __restrict__ dst) {
    long long idx = (long long)blockIdx.x * blockDim.x + threadIdx.x;
    if (idx >= (long long)ET * 4) return;
    int e = (int)(idx >> 2), h = (int)(idx & 3);
    int s, d;
    const float* row;
    if (e < EE) { s = src[e]; d = dst[e]; row = ea + (size_t)e * ED; }
    else        { s = d = e - EE; row = d_mean_ea + (size_t)(e - EE) * ED; }
    float ec = 0.f;
#pragma unroll
    for (int k = 0; k < ED; k++) ec += row[k] * d_c1[k * 4 + h];
    float a = d_als1[s * 4 + h] + d_ald1[d * 4 + h] + ec;
    a = a > 0.f ? a : NEG * a;
    d_alpha1[idx] = a;
    atomicMax(&d_m1[d * 4 + h], fenc(a));
}
__global__ void exp_sum1(const int* __restrict__ dst) {
    long long idx = (long long)blockIdx.x * blockDim.x + threadIdx.x;
    if (idx >= (long long)ET * 4) return;
    int e = (int)(idx >> 2), h = (int)(idx & 3);
    int d = (e < EE) ? dst[e] : e - EE;
    float ex = expf(d_alpha1[idx] - fdec(d_m1[d * 4 + h]));
    d_alpha1[idx] = ex;
    atomicAdd(&d_s1[d * 4 + h], ex);
}
__global__ void edge_alpha2(const float* __restrict__ ea, const int* __restrict__ src,
                            const int* __restrict__ dst) {
    int e = blockIdx.x * blockDim.x + threadIdx.x;
    if (e >= ET) return;
    int s, d;
    const float* row;
    if (e < EE) { s = src[e]; d = dst[e]; row = ea + (size_t)e * ED; }
    else        { s = d = e - EE; row = d_mean_ea + (size_t)(e - EE) * ED; }
    float ec = 0.f;
#pragma unroll
    for (int k = 0; k < ED; k++) ec += row[k] * d_c2[k];
    float a = d_als2[s] + d_ald2[d] + ec;
    a = a > 0.f ? a : NEG * a;
    d_alpha2[e] = a;
    atomicMax(&d_m2[d], fenc(a));
}
__global__ void exp_sum2(const int* __restrict__ dst) {
    int e = blockIdx.x * blockDim.x + threadIdx.x;
    if (e >= ET) return;
    int d = (e < EE) ? dst[e] : e - EE;
    float ex = expf(d_alpha2[e] - fdec(d_m2[d]));
    d_alpha2[e] = ex;
    atomicAdd(&d_s2[d], ex);
}

// ------------------- init out with bias --------------------------------------
__global__ void init_bias(float* out, const float* __restrict__ bias, int C, int total) {
    int idx = blockIdx.x * blockDim.x + threadIdx.x;
    if (idx < total) out[idx] = bias[idx % C];
}

// ------------------- weighted scatter ----------------------------------------
__global__ void scatter1(const int* __restrict__ src, const int* __restrict__ dst) {
    int e = blockIdx.x;
    int t = threadIdx.x;           // 256: h = t>>6
    int s, d;
    if (e < EE) { s = src[e]; d = dst[e]; }
    else        { s = d = e - EE; }
    int h = t >> 6;
    float w = d_alpha1[(size_t)e * 4 + h] / d_s1[d * 4 + h];
    atomicAdd(&d_out1[(size_t)d * C1 + t], d_xs1[(size_t)s * C1 + t] * w);
}
__global__ void scatter2(const int* __restrict__ src, const int* __restrict__ dst) {
    long long idx = (long long)blockIdx.x * blockDim.x + threadIdx.x;
    if (idx >= (long long)ET * HID) return;
    int e = (int)(idx >> 6), t = (int)(idx & 63);
    int s, d;
    if (e < EE) { s = src[e]; d = dst[e]; }
    else        { s = d = e - EE; }
    float w = d_alpha2[e] / d_s2[d];
    atomicAdd(&d_out2[(size_t)d * HID + t], d_xs2[(size_t)s * HID + t] * w);
}

// ------------------- batchnorm ------------------------------------------------
__global__ void bn_stats(const float* __restrict__ X, int C) {
    int t = threadIdx.x;           // blockDim.x == C
    int rows_per = (NN + gridDim.x - 1) / gridDim.x;
    int r0 = blockIdx.x * rows_per;
    int r1 = r0 + rows_per; if (r1 > NN) r1 = NN;
    float s = 0.f, q = 0.f;
    for (int r = r0; r < r1; r++) {
        float v = X[(size_t)r * C + t];
        s += v;
        q += v * v;
    }
    atomicAdd(&d_colsum[t], s);
    atomicAdd(&d_colsq[t], q);
}
__global__ void bn_apply_relu(float* X, const float* __restrict__ g,
                              const float* __restrict__ b, int C, int total) {
    int idx = blockIdx.x * blockDim.x + threadIdx.x;
    if (idx >= total) return;
    int t = idx % C;
    float mu = d_colsum[t] / (float)NN;
    float var = d_colsq[t] / (float)NN - mu * mu;
    float y = (X[idx] - mu) * rsqrtf(var + EPS) * g[t] + b[t];
    X[idx] = y > 0.f ? y : 0.f;
}

// ------------------- pooling ---------------------------------------------------
__global__ void gate_kernel(const float* __restrict__ Wg, const float* __restrict__ bg,
                            const int* __restrict__ batch) {
    int n = blockIdx.x * blockDim.x + threadIdx.x;
    if (n >= NN) return;
    const float* xr = d_out2 + (size_t)n * HID;
    float s = bg[0];
#pragma unroll
    for (int f = 0; f < HID; f++) s += xr[f] * Wg[f];
    d_gate[n] = s;
    atomicMax(&d_gm[batch[n]], fenc(s));
}
__global__ void gate_exp_sum(const int* __restrict__ batch) {
    int n = blockIdx.x * blockDim.x + threadIdx.x;
    if (n >= NN) return;
    int b = batch[n];
    float ex = expf(d_gate[n] - fdec(d_gm[b]));
    d_gate[n] = ex;
    atomicAdd(&d_gs[b], ex);
}
__global__ void pool_scatter(const int* __restrict__ batch, float* __restrict__ out) {
    int idx = blockIdx.x * blockDim.x + threadIdx.x;
    if (idx >= NN * HID) return;
    int n = idx >> 6, c = idx & 63;
    int b = batch[n];
    float w = d_gate[n] / d_gs[b];
    atomicAdd(&out[b * HID + c], d_out2[(size_t)n * HID + c] * w);
}

// ------------------- launch ----------------------------------------------------
static inline int gdiv(long long a, int b) { return (int)((a + b - 1) / b); }

extern "C" void kernel_launch(void* const* d_in, const int* in_sizes, int n_in,
                              void* d_out, int out_size) {
    const float* x    = (const float*)d_in[0];
    const float* ea   = (const float*)d_in[1];
    const int*   ei   = (const int*)d_in[2];
    const int*   batch= (const int*)d_in[3];
    const float* W1   = (const float*)d_in[4];
    const float* We1  = (const float*)d_in[5];
    const float* as1  = (const float*)d_in[6];
    const float* ad1  = (const float*)d_in[7];
    const float* ae1  = (const float*)d_in[8];
    const float* b1   = (const float*)d_in[9];
    const float* g1   = (const float*)d_in[10];
    const float* bb1  = (const float*)d_in[11];
    const float* W2   = (const float*)d_in[12];
    const float* We2  = (const float*)d_in[13];
    const float* as2  = (const float*)d_in[14];
    const float* ad2  = (const float*)d_in[15];
    const float* ae2  = (const float*)d_in[16];
    const float* b2   = (const float*)d_in[17];
    const float* g2   = (const float*)d_in[18];
    const float* bb2  = (const float*)d_in[19];
    const float* Wg   = (const float*)d_in[20];
    const float* bg   = (const float*)d_in[21];
    float* out = (float*)d_out;

    const int* src = ei;
    const int* dst = ei + EE;

    float*    p_mean;   cudaGetSymbolAddress((void**)&p_mean, d_mean_ea);
    float*    p_cnt;    cudaGetSymbolAddress((void**)&p_cnt, d_cnt);
    unsigned* p_m1;     cudaGetSymbolAddress((void**)&p_m1, d_m1);
    float*    p_s1;     cudaGetSymbolAddress((void**)&p_s1, d_s1);
    unsigned* p_m2;     cudaGetSymbolAddress((void**)&p_m2, d_m2);
    float*    p_s2;     cudaGetSymbolAddress((void**)&p_s2, d_s2);
    float*    p_colsum; cudaGetSymbolAddress((void**)&p_colsum, d_colsum);
    float*    p_colsq;  cudaGetSymbolAddress((void**)&p_colsq, d_colsq);
    unsigned* p_gm;     cudaGetSymbolAddress((void**)&p_gm, d_gm);
    float*    p_gs;     cudaGetSymbolAddress((void**)&p_gs, d_gs);
    float*    p_xs1;    cudaGetSymbolAddress((void**)&p_xs1, d_xs1);
    float*    p_out1;   cudaGetSymbolAddress((void**)&p_out1, d_out1);
    float*    p_xs2;    cudaGetSymbolAddress((void**)&p_xs2, d_xs2);
    float*    p_out2;   cudaGetSymbolAddress((void**)&p_out2, d_out2);

    // ---- init scratch ----
    fill_f<<<gdiv(NN * ED, 256), 256>>>(p_mean, 0.f, NN * ED);
    fill_f<<<gdiv(NN, 256), 256>>>(p_cnt, 0.f, NN);
    fill_u<<<gdiv(NN * 4, 256), 256>>>(p_m1, 0u, NN * 4);
    fill_f<<<gdiv(NN * 4, 256), 256>>>(p_s1, 0.f, NN * 4);
    fill_u<<<gdiv(NN, 256), 256>>>(p_m2, 0u, NN);
    fill_f<<<gdiv(NN, 256), 256>>>(p_s2, 0.f, NN);
    fill_f<<<1, 256>>>(p_colsum, 0.f, C1);
    fill_f<<<1, 256>>>(p_colsq, 0.f, C1);
    fill_u<<<1, 64>>>(p_gm, 0u, BB);
    fill_f<<<1, 64>>>(p_gs, 0.f, BB);
    fill_f<<<gdiv(BB * HID, 256), 256>>>(out, 0.f, BB * HID);

    // ---- self-loop mean edge attrs ----
    ea_mean_accum<<<gdiv((long long)EE * ED, 256), 256>>>(ea, dst);
    ea_mean_div<<<gdiv(NN * ED, 256), 256>>>();

    // ---- layer 1 ----
    {
        dim3 g(C1 / 16, NN / 16);
        gemm_tiled<<<g, dim3(16, 16)>>>(x, W1, p_xs1, NN, FIN, C1);
    }
    al_kernel1<<<gdiv(NN * 4, 256), 256>>>(as1, ad1);
    c1_kernel<<<1, 128>>>(We1, ae1);
    edge_alpha1<<<gdiv((long long)ET * 4, 256), 256>>>(ea, src, dst);
    exp_sum1<<<gdiv((long long)ET * 4, 256), 256>>>(dst);
    init_bias<<<gdiv(NN * C1, 256), 256>>>(p_out1, b1, C1, NN * C1);
    scatter1<<<ET, 256>>>(src, dst);
    bn_stats<<<128, C1>>>(p_out1, C1);
    bn_apply_relu<<<gdiv(NN * C1, 256), 256>>>(p_out1, g1, bb1, C1, NN * C1);

    // ---- layer 2 ----
    {
        dim3 g(HID / 16, NN / 16);
        gemm_tiled<<<g, dim3(16, 16)>>>(p_out1, W2, p_xs2, NN, C1, HID);
    }
    al_kernel2<<<gdiv(NN, 256), 256>>>(as2, ad2);
    c2_kernel<<<1, 32>>>(We2, ae2);
    edge_alpha2<<<gdiv(ET, 256), 256>>>(ea, src, dst);
    exp_sum2<<<gdiv(ET, 256), 256>>>(dst);
    init_bias<<<gdiv(NN * HID, 256), 256>>>(p_out2, b2, HID, NN * HID);
    scatter2<<<gdiv((long long)ET * HID, 256), 256>>>(src, dst);
    fill_f<<<1, 64>>>(p_colsum, 0.f, HID);
    fill_f<<<1, 64>>>(p_colsq, 0.f, HID);
    bn_stats<<<128, HID>>>(p_out2, HID);
    bn_apply_relu<<<gdiv(NN * HID, 256), 256>>>(p_out2, g2, bb2, HID, NN * HID);

    // ---- pooling ----
    gate_kernel<<<gdiv(NN, 256), 256>>>(Wg, bg, batch);
    gate_exp_sum<<<gdiv(NN, 256), 256>>>(batch);
    pool_scatter<<<gdiv(NN * HID, 256), 256>>>(batch, out);
}

// round 3
// speedup vs baseline: 2.8465x; 2.8465x over previous
#include <cuda_runtime.h>

#define NN 30000
#define EE 480000
#define ET (EE + NN)   // edges incl. self loops
#define BB 64
#define FIN 128
#define HID 64
#define ED 32
#define C1 256         // 4*HID
#define NEG 0.2f
#define EPS 1e-5f

// ------------------- scratch -------------------------------------------------
__device__ int      d_deg[NN];
__device__ int      d_rowptr[NN + 1];
__device__ int      d_cursor[NN];
__device__ int      d_esrc[ET];    // src node per CSR slot
__device__ int      d_eid[ET];     // original edge id per CSR slot
__device__ int      d_edst[ET];    // dst node per CSR slot
__device__ int      d_pos[ET];     // CSR slot of original edge id

__device__ float    d_mean_ea[NN * ED];
__device__ float    d_xs1[(size_t)NN * C1];
__device__ float    d_als1[NN * 4];
__device__ float    d_ald1[NN * 4];
__device__ float    d_c1[ED * 4];
__device__ float    d_alpha1[(size_t)ET * 4];   // CSR-ordered
__device__ unsigned d_m1[NN * 4];
__device__ float    d_s1[NN * 4];
__device__ float    d_out1[(size_t)NN * C1];
__device__ float    d_colsum[C1];
__device__ float    d_colsq[C1];
__device__ float    d_xs2[(size_t)NN * HID];
__device__ float    d_als2[NN];
__device__ float    d_ald2[NN];
__device__ float    d_c2[ED];
__device__ float    d_alpha2[ET];               // CSR-ordered
__device__ unsigned d_m2[NN];
__device__ float    d_s2[NN];
__device__ float    d_out2[(size_t)NN * HID];
__device__ float    d_gate[NN];
__device__ unsigned d_gm[BB];
__device__ float    d_gs[BB];

// ------------------- helpers -------------------------------------------------
__device__ __forceinline__ unsigned fenc(float f) {
    unsigned u = __float_as_uint(f);
    return (u & 0x80000000u) ? ~u : (u | 0x80000000u);
}
__device__ __forceinline__ float fdec(unsigned u) {
    return (u & 0x80000000u) ? __uint_as_float(u & 0x7FFFFFFFu) : __uint_as_float(~u);
}

__global__ void fill_f(float* p, float v, int n) {
    int i = blockIdx.x * blockDim.x + threadIdx.x;
    if (i < n) p[i] = v;
}
__global__ void fill_u(unsigned* p, unsigned v, int n) {
    int i = blockIdx.x * blockDim.x + threadIdx.x;
    if (i < n) p[i] = v;
}
__global__ void fill_i(int* p, int v, int n) {
    int i = blockIdx.x * blockDim.x + threadIdx.x;
    if (i < n) p[i] = v;
}

// ------------------- CSR build -----------------------------------------------
__global__ void hist_kernel(const int* __restrict__ dst) {
    int e = blockIdx.x * blockDim.x + threadIdx.x;
    if (e < EE) atomicAdd(&d_deg[dst[e]], 1);
}

__global__ void scan_kernel() {
    __shared__ int wsum[32];
    const int PER = 30;                    // 1024*30 = 30720 >= NN
    int t = threadIdx.x;
    int base = t * PER;
    int vals[PER];
    int s = 0;
#pragma unroll
    for (int i = 0; i < PER; i++) {
        int idx = base + i;
        vals[i] = (idx < NN) ? d_deg[idx] : 0;
        s += vals[i];
    }
    int lane = t & 31, w = t >> 5;
    int x = s;
#pragma unroll
    for (int off = 1; off < 32; off <<= 1) {
        int y = __shfl_up_sync(0xFFFFFFFFu, x, off);
        if (lane >= off) x += y;
    }
    if (lane == 31) wsum[w] = x;
    __syncthreads();
    if (w == 0) {
        int y = wsum[lane];
#pragma unroll
        for (int off = 1; off < 32; off <<= 1) {
            int z = __shfl_up_sync(0xFFFFFFFFu, y, off);
            if (lane >= off) y += z;
        }
        wsum[lane] = y;
    }
    __syncthreads();
    int excl = x - s + (w > 0 ? wsum[w - 1] : 0);
    int run = excl;
#pragma unroll
    for (int i = 0; i < PER; i++) {
        int idx = base + i;
        if (idx < NN) d_rowptr[idx] = run;
        run += vals[i];
    }
    if (t == 0) d_rowptr[NN] = ET;
}

__global__ void csr_fill(const int* __restrict__ src, const int* __restrict__ dst) {
    int e = blockIdx.x * blockDim.x + threadIdx.x;
    if (e >= ET) return;
    int s, d;
    if (e < EE) { s = src[e]; d = dst[e]; }
    else        { s = d = e - EE; }
    int p = d_rowptr[d] + atomicAdd(&d_cursor[d], 1);
    d_esrc[p] = s;
    d_eid[p]  = e;
    d_edst[p] = d;
    d_pos[e]  = p;
}

// ------------------- self-loop mean edge attr (CSR gather) -------------------
__global__ void ea_mean_csr(const float* __restrict__ ea) {
    int warp = (blockIdx.x * blockDim.x + threadIdx.x) >> 5;
    int lane = threadIdx.x & 31;
    if (warp >= NN) return;
    int r0 = d_rowptr[warp], r1 = d_rowptr[warp + 1];
    float s = 0.f;
    int cnt = 0;
    for (int p = r0; p < r1; p++) {
        int e = d_eid[p];
        if (e < EE) { s += ea[(size_t)e * ED + lane]; cnt++; }
    }
    d_mean_ea[warp * ED + lane] = s / (float)(cnt > 1 ? cnt : 1);
}

// ------------------- register-tiled GEMM C = A[M,K] x B[K,N] -----------------
__global__ void gemm_rt(const float* __restrict__ A, const float* __restrict__ B,
                        float* __restrict__ C, int M, int K, int N) {
    const int BM = 64, BN = 64, BK = 16;
    __shared__ float As[BK][BM + 1];
    __shared__ float Bs[BK][BN];
    int tid = threadIdx.x;                   // 256
    int tx = tid & 15, ty = tid >> 4;
    int m0 = blockIdx.y * BM, n0 = blockIdx.x * BN;
    float acc[4][4] = {};
    for (int k0 = 0; k0 < K; k0 += BK) {
#pragma unroll
        for (int i = 0; i < 4; i++) {
            int lin = tid + i * 256;
            int ar = lin >> 4, ak = lin & 15;
            int gr = m0 + ar;
            As[ak][ar] = (gr < M) ? A[(size_t)gr * K + k0 + ak] : 0.f;
        }
#pragma unroll
        for (int i = 0; i < 4; i++) {
            int lin = tid + i * 256;
            int br = lin >> 6, bn = lin & 63;
            Bs[br][bn] = B[(size_t)(k0 + br) * N + n0 + bn];
        }
        __syncthreads();
#pragma unroll
        for (int kk = 0; kk < BK; kk++) {
            float a[4], b[4];
#pragma unroll
            for (int i = 0; i < 4; i++) a[i] = As[kk][ty * 4 + i];
#pragma unroll
            for (int j = 0; j < 4; j++) b[j] = Bs[kk][tx * 4 + j];
#pragma unroll
            for (int i = 0; i < 4; i++)
#pragma unroll
                for (int j = 0; j < 4; j++) acc[i][j] += a[i] * b[j];
        }
        __syncthreads();
    }
#pragma unroll
    for (int i = 0; i < 4; i++) {
        int gr = m0 + ty * 4 + i;
        if (gr < M)
#pragma unroll
            for (int j = 0; j < 4; j++)
                C[(size_t)gr * N + n0 + tx * 4 + j] = acc[i][j];
    }
}

// ------------------- attention logits ----------------------------------------
__global__ void al_kernel1(const float* __restrict__ as, const float* __restrict__ ad) {
    int idx = blockIdx.x * blockDim.x + threadIdx.x;
    if (idx >= NN * 4) return;
    int n = idx >> 2, h = idx & 3;
    const float* xr = d_xs1 + (size_t)n * C1 + h * HID;
    float s = 0.f, d = 0.f;
#pragma unroll
    for (int f = 0; f < HID; f++) {
        float v = xr[f];
        s += v * as[h * HID + f];
        d += v * ad[h * HID + f];
    }
    d_als1[idx] = s;
    d_ald1[idx] = d;
}
__global__ void al_kernel2(const float* __restrict__ as, const float* __restrict__ ad) {
    int n = blockIdx.x * blockDim.x + threadIdx.x;
    if (n >= NN) return;
    const float* xr = d_xs2 + (size_t)n * HID;
    float s = 0.f, d = 0.f;
#pragma unroll
    for (int f = 0; f < HID; f++) {
        float v = xr[f];
        s += v * as[f];
        d += v * ad[f];
    }
    d_als2[n] = s;
    d_ald2[n] = d;
}

__global__ void c1_kernel(const float* __restrict__ We1, const float* __restrict__ ae1) {
    int idx = threadIdx.x;
    if (idx >= ED * 4) return;
    int k = idx >> 2, h = idx & 3;
    float s = 0.f;
#pragma unroll
    for (int f = 0; f < HID; f++) s += We1[k * C1 + h * HID + f] * ae1[h * HID + f];
    d_c1[k * 4 + h] = s;
}
__global__ void c2_kernel(const float* __restrict__ We2, const float* __restrict__ ae2) {
    int k = threadIdx.x;
    if (k >= ED) return;
    float s = 0.f;
#pragma unroll
    for (int f = 0; f < HID; f++) s += We2[k * HID + f] * ae2[f];
    d_c2[k] = s;
}

// ------------------- edge alpha (writes CSR-ordered) ---------------------------
__global__ void edge_alpha1(const float* __restrict__ ea, const int* __restrict__ src,
                            const int* __restrict__ dst) {
    int e = blockIdx.x * blockDim.x + threadIdx.x;
    if (e >= ET) return;
    int s, d;
    const float* row;
    if (e < EE) { s = src[e]; d = dst[e]; row = ea + (size_t)e * ED; }
    else        { s = d = e - EE; row = d_mean_ea + (size_t)(e - EE) * ED; }
    float ec0 = 0.f, ec1 = 0.f, ec2 = 0.f, ec3 = 0.f;
#pragma unroll
    for (int k = 0; k < ED; k++) {
        float v = __ldg(row + k);
        ec0 += v * d_c1[k * 4 + 0];
        ec1 += v * d_c1[k * 4 + 1];
        ec2 += v * d_c1[k * 4 + 2];
        ec3 += v * d_c1[k * 4 + 3];
    }
    float ec[4] = {ec0, ec1, ec2, ec3};
    size_t pb = (size_t)d_pos[e] * 4;
#pragma unroll
    for (int h = 0; h < 4; h++) {
        float a = d_als1[s * 4 + h] + d_ald1[d * 4 + h] + ec[h];
        a = a > 0.f ? a : NEG * a;
        d_alpha1[pb + h] = a;
        atomicMax(&d_m1[d * 4 + h], fenc(a));
    }
}
__global__ void exp_sum1() {
    long long idx = (long long)blockIdx.x * blockDim.x + threadIdx.x;
    if (idx >= (long long)ET * 4) return;
    int p = (int)(idx >> 2), h = (int)(idx & 3);
    int d = d_edst[p];
    float ex = expf(d_alpha1[idx] - fdec(d_m1[d * 4 + h]));
    d_alpha1[idx] = ex;
    atomicAdd(&d_s1[d * 4 + h], ex);
}
__global__ void edge_alpha2(const float* __restrict__ ea, const int* __restrict__ src,
                            const int* __restrict__ dst) {
    int e = blockIdx.x * blockDim.x + threadIdx.x;
    if (e >= ET) return;
    int s, d;
    const float* row;
    if (e < EE) { s = src[e]; d = dst[e]; row = ea + (size_t)e * ED; }
    else        { s = d = e - EE; row = d_mean_ea + (size_t)(e - EE) * ED; }
    float ec = 0.f;
#pragma unroll
    for (int k = 0; k < ED; k++) ec += __ldg(row + k) * d_c2[k];
    float a = d_als2[s] + d_ald2[d] + ec;
    a = a > 0.f ? a : NEG * a;
    d_alpha2[d_pos[e]] = a;
    atomicMax(&d_m2[d], fenc(a));
}
__global__ void exp_sum2() {
    int p = blockIdx.x * blockDim.x + threadIdx.x;
    if (p >= ET) return;
    int d = d_edst[p];
    float ex = expf(d_alpha2[p] - fdec(d_m2[d]));
    d_alpha2[p] = ex;
    atomicAdd(&d_s2[d], ex);
}

// ------------------- CSR gather (no atomics) ----------------------------------
__global__ void gather1(const float* __restrict__ bias) {
    int d = blockIdx.x;
    int t = threadIdx.x;          // 256, channel
    int h = t >> 6;
    __shared__ float sh_sinv[4];
    __shared__ int   sh_src[32];
    __shared__ float sh_w[32 * 4];
    if (t < 4) sh_sinv[t] = 1.0f / d_s1[d * 4 + t];
    int r0 = d_rowptr[d], r1 = d_rowptr[d + 1];
    __syncthreads();
    float sinv = sh_sinv[h];
    float acc = 0.f;
    for (int p0 = r0; p0 < r1; p0 += 32) {
        int m = min(32, r1 - p0);
        __syncthreads();
        if (t < m * 4) sh_w[t] = d_alpha1[(size_t)p0 * 4 + t];
        if (t < m)     sh_src[t] = d_esrc[p0 + t];
        __syncthreads();
        for (int j = 0; j < m; j++)
            acc += sh_w[j * 4 + h] * d_xs1[(size_t)sh_src[j] * C1 + t];
    }
    d_out1[(size_t)d * C1 + t] = acc * sinv + bias[t];
}
__global__ void gather2(const float* __restrict__ bias) {
    int d = blockIdx.x;
    int t = threadIdx.x;          // 64
    __shared__ int   sh_src[64];
    __shared__ float sh_w[64];
    int r0 = d_rowptr[d], r1 = d_rowptr[d + 1];
    float sinv = 1.0f / d_s2[d];
    float acc = 0.f;
    for (int p0 = r0; p0 < r1; p0 += 64) {
        int m = min(64, r1 - p0);
        __syncthreads();
        if (t < m) {
            sh_w[t]   = d_alpha2[p0 + t];
            sh_src[t] = d_esrc[p0 + t];
        }
        __syncthreads();
        for (int j = 0; j < m; j++)
            acc += sh_w[j] * d_xs2[(size_t)sh_src[j] * HID + t];
    }
    d_out2[(size_t)d * HID + t] = acc * sinv + bias[t];
}

// ------------------- batchnorm -------------------------------------------------
__global__ void bn_stats(const float* __restrict__ X, int C) {
    int t = threadIdx.x;
    int rows_per = (NN + gridDim.x - 1) / gridDim.x;
    int r0 = blockIdx.x * rows_per;
    int r1 = r0 + rows_per; if (r1 > NN) r1 = NN;
    float s = 0.f, q = 0.f;
    for (int r = r0; r < r1; r++) {
        float v = X[(size_t)r * C + t];
        s += v;
        q += v * v;
    }
    atomicAdd(&d_colsum[t], s);
    atomicAdd(&d_colsq[t], q);
}
__global__ void bn_apply_relu(float* X, const float* __restrict__ g,
                              const float* __restrict__ b, int C, int total) {
    int idx = blockIdx.x * blockDim.x + threadIdx.x;
    if (idx >= total) return;
    int t = idx % C;
    float mu = d_colsum[t] / (float)NN;
    float var = d_colsq[t] / (float)NN - mu * mu;
    float y = (X[idx] - mu) * rsqrtf(var + EPS) * g[t] + b[t];
    X[idx] = y > 0.f ? y : 0.f;
}

// ------------------- pooling ----------------------------------------------------
__global__ void gate_kernel(const float* __restrict__ Wg, const float* __restrict__ bg,
                            const int* __restrict__ batch) {
    int n = blockIdx.x * blockDim.x + threadIdx.x;
    if (n >= NN) return;
    const float* xr = d_out2 + (size_t)n * HID;
    float s = bg[0];
#pragma unroll
    for (int f = 0; f < HID; f++) s += xr[f] * Wg[f];
    d_gate[n] = s;
    atomicMax(&d_gm[batch[n]], fenc(s));
}
__global__ void gate_exp_sum(const int* __restrict__ batch) {
    int n = blockIdx.x * blockDim.x + threadIdx.x;
    if (n >= NN) return;
    int b = batch[n];
    float ex = expf(d_gate[n] - fdec(d_gm[b]));
    d_gate[n] = ex;
    atomicAdd(&d_gs[b], ex);
}
__global__ void pool_scatter(const int* __restrict__ batch, float* __restrict__ out) {
    int idx = blockIdx.x * blockDim.x + threadIdx.x;
    if (idx >= NN * HID) return;
    int n = idx >> 6, c = idx & 63;
    int b = batch[n];
    float w = d_gate[n] / d_gs[b];
    atomicAdd(&out[b * HID + c], d_out2[(size_t)n * HID + c] * w);
}

// ------------------- launch ------------------------------------------------------
static inline int gdiv(long long a, int b) { return (int)((a + b - 1) / b); }

extern "C" void kernel_launch(void* const* d_in, const int* in_sizes, int n_in,
                              void* d_out, int out_size) {
    const float* x     = (const float*)d_in[0];
    const float* ea    = (const float*)d_in[1];
    const int*   ei    = (const int*)d_in[2];
    const int*   batch = (const int*)d_in[3];
    const float* W1    = (const float*)d_in[4];
    const float* We1   = (const float*)d_in[5];
    const float* as1   = (const float*)d_in[6];
    const float* ad1   = (const float*)d_in[7];
    const float* ae1   = (const float*)d_in[8];
    const float* b1    = (const float*)d_in[9];
    const float* g1    = (const float*)d_in[10];
    const float* bb1   = (const float*)d_in[11];
    const float* W2    = (const float*)d_in[12];
    const float* We2   = (const float*)d_in[13];
    const float* as2   = (const float*)d_in[14];
    const float* ad2   = (const float*)d_in[15];
    const float* ae2   = (const float*)d_in[16];
    const float* b2    = (const float*)d_in[17];
    const float* g2    = (const float*)d_in[18];
    const float* bb2   = (const float*)d_in[19];
    const float* Wg    = (const float*)d_in[20];
    const float* bg    = (const float*)d_in[21];
    float* out = (float*)d_out;

    const int* src = ei;
    const int* dst = ei + EE;

    int*      p_deg;    cudaGetSymbolAddress((void**)&p_deg, d_deg);
    int*      p_cursor; cudaGetSymbolAddress((void**)&p_cursor, d_cursor);
    unsigned* p_m1;     cudaGetSymbolAddress((void**)&p_m1, d_m1);
    float*    p_s1;     cudaGetSymbolAddress((void**)&p_s1, d_s1);
    unsigned* p_m2;     cudaGetSymbolAddress((void**)&p_m2, d_m2);
    float*    p_s2;     cudaGetSymbolAddress((void**)&p_s2, d_s2);
    float*    p_colsum; cudaGetSymbolAddress((void**)&p_colsum, d_colsum);
    float*    p_colsq;  cudaGetSymbolAddress((void**)&p_colsq, d_colsq);
    unsigned* p_gm;     cudaGetSymbolAddress((void**)&p_gm, d_gm);
    float*    p_gs;     cudaGetSymbolAddress((void**)&p_gs, d_gs);
    float*    p_xs1;    cudaGetSymbolAddress((void**)&p_xs1, d_xs1);
    float*    p_out1;   cudaGetSymbolAddress((void**)&p_out1, d_out1);
    float*    p_xs2;    cudaGetSymbolAddress((void**)&p_xs2, d_xs2);
    float*    p_out2;   cudaGetSymbolAddress((void**)&p_out2, d_out2);

    // ---- init ----
    fill_i<<<gdiv(NN, 256), 256>>>(p_deg, 1, NN);          // self loop
    fill_i<<<gdiv(NN, 256), 256>>>(p_cursor, 0, NN);
    fill_u<<<gdiv(NN * 4, 256), 256>>>(p_m1, 0u, NN * 4);
    fill_f<<<gdiv(NN * 4, 256), 256>>>(p_s1, 0.f, NN * 4);
    fill_u<<<gdiv(NN, 256), 256>>>(p_m2, 0u, NN);
    fill_f<<<gdiv(NN, 256), 256>>>(p_s2, 0.f, NN);
    fill_f<<<1, 256>>>(p_colsum, 0.f, C1);
    fill_f<<<1, 256>>>(p_colsq, 0.f, C1);
    fill_u<<<1, 64>>>(p_gm, 0u, BB);
    fill_f<<<1, 64>>>(p_gs, 0.f, BB);
    fill_f<<<gdiv(BB * HID, 256), 256>>>(out, 0.f, BB * HID);

    // ---- CSR build ----
    hist_kernel<<<gdiv(EE, 256), 256>>>(dst);
    scan_kernel<<<1, 1024>>>();
    csr_fill<<<gdiv(ET, 256), 256>>>(src, dst);

    // ---- self-loop mean edge attrs ----
    ea_mean_csr<<<gdiv(NN * 32, 256), 256>>>(ea);

    // ---- layer 1 ----
    {
        dim3 g(C1 / 64, gdiv(NN, 64));
        gemm_rt<<<g, 256>>>(x, W1, p_xs1, NN, FIN, C1);
    }
    al_kernel1<<<gdiv(NN * 4, 256), 256>>>(as1, ad1);
    c1_kernel<<<1, 128>>>(We1, ae1);
    edge_alpha1<<<gdiv(ET, 256), 256>>>(ea, src, dst);
    exp_sum1<<<gdiv((long long)ET * 4, 256), 256>>>();
    gather1<<<NN, 256>>>(b1);
    bn_stats<<<128, C1>>>(p_out1, C1);
    bn_apply_relu<<<gdiv(NN * C1, 256), 256>>>(p_out1, g1, bb1, C1, NN * C1);

    // ---- layer 2 ----
    {
        dim3 g(HID / 64, gdiv(NN, 64));
        gemm_rt<<<g, 256>>>(p_out1, W2, p_xs2, NN, C1, HID);
    }
    al_kernel2<<<gdiv(NN, 256), 256>>>(as2, ad2);
    c2_kernel<<<1, 32>>>(We2, ae2);
    edge_alpha2<<<gdiv(ET, 256), 256>>>(ea, src, dst);
    exp_sum2<<<gdiv(ET, 256), 256>>>();
    gather2<<<NN, 64>>>(b2);
    fill_f<<<1, 64>>>(p_colsum, 0.f, HID);
    fill_f<<<1, 64>>>(p_colsq, 0.f, HID);
    bn_stats<<<128, HID>>>(p_out2, HID);
    bn_apply_relu<<<gdiv(NN * HID, 256), 256>>>(p_out2, g2, bb2, HID, NN * HID);

    // ---- pooling ----
    gate_kernel<<<gdiv(NN, 256), 256>>>(Wg, bg, batch);
    gate_exp_sum<<<gdiv(NN, 256), 256>>>(batch);
    pool_scatter<<<gdiv(NN * HID, 256), 256>>>(batch, out);
}

// round 4
// speedup vs baseline: 2.8474x; 1.0003x over previous
#include <cuda_runtime.h>

#define NN 30000
#define EE 480000
#define ET (EE + NN)   // edges incl. self loops
#define BB 64
#define FIN 128
#define HID 64
#define ED 32
#define C1 256         // 4*HID
#define NEG 0.2f
#define EPS 1e-5f

// ------------------- scratch -------------------------------------------------
__device__ int      d_deg[NN];
__device__ int      d_rowptr[NN + 1];
__device__ int      d_cursor[NN];
__device__ int      d_esrc[ET];    // src node per CSR slot
__device__ int      d_eid[ET];     // original edge id per CSR slot
__device__ int      d_edst[ET];    // dst node per CSR slot
__device__ int      d_pos[ET];     // CSR slot of original edge id

__device__ float    d_mean_ea[NN * ED];
__device__ float    d_xs1[(size_t)NN * C1];
__device__ float    d_als1[NN * 4];
__device__ float    d_ald1[NN * 4];
__device__ float    d_c1[ED * 4];
__device__ float    d_alpha1[(size_t)ET * 4];   // CSR-ordered
__device__ unsigned d_m1[NN * 4];
__device__ float    d_s1[NN * 4];
__device__ float    d_out1[(size_t)NN * C1];
__device__ float    d_colsum[C1];
__device__ float    d_colsq[C1];
__device__ float    d_xs2[(size_t)NN * HID];
__device__ float    d_als2[NN];
__device__ float    d_ald2[NN];
__device__ float    d_c2[ED];
__device__ float    d_alpha2[ET];               // CSR-ordered
__device__ unsigned d_m2[NN];
__device__ float    d_s2[NN];
__device__ float    d_out2[(size_t)NN * HID];
__device__ float    d_gate[NN];
__device__ unsigned d_gm[BB];
__device__ float    d_gs[BB];

// ------------------- helpers -------------------------------------------------
__device__ __forceinline__ unsigned fenc(float f) {
    unsigned u = __float_as_uint(f);
    return (u & 0x80000000u) ? ~u : (u | 0x80000000u);
}
__device__ __forceinline__ float fdec(unsigned u) {
    return (u & 0x80000000u) ? __uint_as_float(u & 0x7FFFFFFFu) : __uint_as_float(~u);
}

__global__ void fill_f(float* p, float v, int n) {
    int i = blockIdx.x * blockDim.x + threadIdx.x;
    if (i < n) p[i] = v;
}
__global__ void fill_u(unsigned* p, unsigned v, int n) {
    int i = blockIdx.x * blockDim.x + threadIdx.x;
    if (i < n) p[i] = v;
}
__global__ void fill_i(int* p, int v, int n) {
    int i = blockIdx.x * blockDim.x + threadIdx.x;
    if (i < n) p[i] = v;
}

// ------------------- CSR build -----------------------------------------------
__global__ void hist_kernel(const int* __restrict__ dst) {
    int e = blockIdx.x * blockDim.x + threadIdx.x;
    if (e < EE) atomicAdd(&d_deg[dst[e]], 1);
}

__global__ void scan_kernel() {
    __shared__ int wsum[32];
    const int PER = 30;                    // 1024*30 = 30720 >= NN
    int t = threadIdx.x;
    int base = t * PER;
    int vals[PER];
    int s = 0;
#pragma unroll
    for (int i = 0; i < PER; i++) {
        int idx = base + i;
        vals[i] = (idx < NN) ? d_deg[idx] : 0;
        s += vals[i];
    }
    int lane = t & 31, w = t >> 5;
    int x = s;
#pragma unroll
    for (int off = 1; off < 32; off <<= 1) {
        int y = __shfl_up_sync(0xFFFFFFFFu, x, off);
        if (lane >= off) x += y;
    }
    if (lane == 31) wsum[w] = x;
    __syncthreads();
    if (w == 0) {
        int y = wsum[lane];
#pragma unroll
        for (int off = 1; off < 32; off <<= 1) {
            int z = __shfl_up_sync(0xFFFFFFFFu, y, off);
            if (lane >= off) y += z;
        }
        wsum[lane] = y;
    }
    __syncthreads();
    int excl = x - s + (w > 0 ? wsum[w - 1] : 0);
    int run = excl;
#pragma unroll
    for (int i = 0; i < PER; i++) {
        int idx = base + i;
        if (idx < NN) d_rowptr[idx] = run;
        run += vals[i];
    }
    if (t == 0) d_rowptr[NN] = ET;
}

__global__ void csr_fill(const int* __restrict__ src, const int* __restrict__ dst) {
    int e = blockIdx.x * blockDim.x + threadIdx.x;
    if (e >= ET) return;
    int s, d;
    if (e < EE) { s = src[e]; d = dst[e]; }
    else        { s = d = e - EE; }
    int p = d_rowptr[d] + atomicAdd(&d_cursor[d], 1);
    d_esrc[p] = s;
    d_eid[p]  = e;
    d_edst[p] = d;
    d_pos[e]  = p;
}

// ------------------- self-loop mean edge attr (CSR gather) -------------------
__global__ void ea_mean_csr(const float* __restrict__ ea) {
    int warp = (blockIdx.x * blockDim.x + threadIdx.x) >> 5;
    int lane = threadIdx.x & 31;
    if (warp >= NN) return;
    int r0 = d_rowptr[warp], r1 = d_rowptr[warp + 1];
    float s = 0.f;
    int cnt = 0;
    for (int p = r0; p < r1; p++) {
        int e = d_eid[p];
        if (e < EE) { s += ea[(size_t)e * ED + lane]; cnt++; }
    }
    d_mean_ea[warp * ED + lane] = s / (float)(cnt > 1 ? cnt : 1);
}

// ------------------- register-tiled GEMM C = A[M,K] x B[K,N] -----------------
__global__ void gemm_rt(const float* __restrict__ A, const float* __restrict__ B,
                        float* __restrict__ C, int M, int K, int N) {
    const int BM = 64, BN = 64, BK = 16;
    __shared__ float As[BK][BM + 1];
    __shared__ float Bs[BK][BN];
    int tid = threadIdx.x;                   // 256
    int tx = tid & 15, ty = tid >> 4;
    int m0 = blockIdx.y * BM, n0 = blockIdx.x * BN;
    float acc[4][4] = {};
    for (int k0 = 0; k0 < K; k0 += BK) {
#pragma unroll
        for (int i = 0; i < 4; i++) {
            int lin = tid + i * 256;
            int ar = lin >> 4, ak = lin & 15;
            int gr = m0 + ar;
            As[ak][ar] = (gr < M) ? A[(size_t)gr * K + k0 + ak] : 0.f;
        }
#pragma unroll
        for (int i = 0; i < 4; i++) {
            int lin = tid + i * 256;
            int br = lin >> 6, bn = lin & 63;
            Bs[br][bn] = B[(size_t)(k0 + br) * N + n0 + bn];
        }
        __syncthreads();
#pragma unroll
        for (int kk = 0; kk < BK; kk++) {
            float a[4], b[4];
#pragma unroll
            for (int i = 0; i < 4; i++) a[i] = As[kk][ty * 4 + i];
#pragma unroll
            for (int j = 0; j < 4; j++) b[j] = Bs[kk][tx * 4 + j];
#pragma unroll
            for (int i = 0; i < 4; i++)
#pragma unroll
                for (int j = 0; j < 4; j++) acc[i][j] += a[i] * b[j];
        }
        __syncthreads();
    }
#pragma unroll
    for (int i = 0; i < 4; i++) {
        int gr = m0 + ty * 4 + i;
        if (gr < M)
#pragma unroll
            for (int j = 0; j < 4; j++)
                C[(size_t)gr * N + n0 + tx * 4 + j] = acc[i][j];
    }
}

// ------------------- attention logits ----------------------------------------
__global__ void al_kernel1(const float* __restrict__ as, const float* __restrict__ ad) {
    int idx = blockIdx.x * blockDim.x + threadIdx.x;
    if (idx >= NN * 4) return;
    int n = idx >> 2, h = idx & 3;
    const float* xr = d_xs1 + (size_t)n * C1 + h * HID;
    float s = 0.f, d = 0.f;
#pragma unroll
    for (int f = 0; f < HID; f++) {
        float v = xr[f];
        s += v * as[h * HID + f];
        d += v * ad[h * HID + f];
    }
    d_als1[idx] = s;
    d_ald1[idx] = d;
}
__global__ void al_kernel2(const float* __restrict__ as, const float* __restrict__ ad) {
    int n = blockIdx.x * blockDim.x + threadIdx.x;
    if (n >= NN) return;
    const float* xr = d_xs2 + (size_t)n * HID;
    float s = 0.f, d = 0.f;
#pragma unroll
    for (int f = 0; f < HID; f++) {
        float v = xr[f];
        s += v * as[f];
        d += v * ad[f];
    }
    d_als2[n] = s;
    d_ald2[n] = d;
}

__global__ void c1_kernel(const float* __restrict__ We1, const float* __restrict__ ae1) {
    int idx = threadIdx.x;
    if (idx >= ED * 4) return;
    int k = idx >> 2, h = idx & 3;
    float s = 0.f;
#pragma unroll
    for (int f = 0; f < HID; f++) s += We1[k * C1 + h * HID + f] * ae1[h * HID + f];
    d_c1[k * 4 + h] = s;
}
__global__ void c2_kernel(const float* __restrict__ We2, const float* __restrict__ ae2) {
    int k = threadIdx.x;
    if (k >= ED) return;
    float s = 0.f;
#pragma unroll
    for (int f = 0; f < HID; f++) s += We2[k * HID + f] * ae2[f];
    d_c2[k] = s;
}

// ------------------- edge alpha (writes CSR-ordered) ---------------------------
__global__ void edge_alpha1(const float* __restrict__ ea, const int* __restrict__ src,
                            const int* __restrict__ dst) {
    int e = blockIdx.x * blockDim.x + threadIdx.x;
    if (e >= ET) return;
    int s, d;
    const float* row;
    if (e < EE) { s = src[e]; d = dst[e]; row = ea + (size_t)e * ED; }
    else        { s = d = e - EE; row = d_mean_ea + (size_t)(e - EE) * ED; }
    float ec0 = 0.f, ec1 = 0.f, ec2 = 0.f, ec3 = 0.f;
#pragma unroll
    for (int k = 0; k < ED; k++) {
        float v = __ldg(row + k);
        ec0 += v * d_c1[k * 4 + 0];
        ec1 += v * d_c1[k * 4 + 1];
        ec2 += v * d_c1[k * 4 + 2];
        ec3 += v * d_c1[k * 4 + 3];
    }
    float ec[4] = {ec0, ec1, ec2, ec3};
    size_t pb = (size_t)d_pos[e] * 4;
#pragma unroll
    for (int h = 0; h < 4; h++) {
        float a = d_als1[s * 4 + h] + d_ald1[d * 4 + h] + ec[h];
        a = a > 0.f ? a : NEG * a;
        d_alpha1[pb + h] = a;
        atomicMax(&d_m1[d * 4 + h], fenc(a));
    }
}
__global__ void exp_sum1() {
    long long idx = (long long)blockIdx.x * blockDim.x + threadIdx.x;
    if (idx >= (long long)ET * 4) return;
    int p = (int)(idx >> 2), h = (int)(idx & 3);
    int d = d_edst[p];
    float ex = expf(d_alpha1[idx] - fdec(d_m1[d * 4 + h]));
    d_alpha1[idx] = ex;
    atomicAdd(&d_s1[d * 4 + h], ex);
}
__global__ void edge_alpha2(const float* __restrict__ ea, const int* __restrict__ src,
                            const int* __restrict__ dst) {
    int e = blockIdx.x * blockDim.x + threadIdx.x;
    if (e >= ET) return;
    int s, d;
    const float* row;
    if (e < EE) { s = src[e]; d = dst[e]; row = ea + (size_t)e * ED; }
    else        { s = d = e - EE; row = d_mean_ea + (size_t)(e - EE) * ED; }
    float ec = 0.f;
#pragma unroll
    for (int k = 0; k < ED; k++) ec += __ldg(row + k) * d_c2[k];
    float a = d_als2[s] + d_ald2[d] + ec;
    a = a > 0.f ? a : NEG * a;
    d_alpha2[d_pos[e]] = a;
    atomicMax(&d_m2[d], fenc(a));
}
__global__ void exp_sum2() {
    int p = blockIdx.x * blockDim.x + threadIdx.x;
    if (p >= ET) return;
    int d = d_edst[p];
    float ex = expf(d_alpha2[p] - fdec(d_m2[d]));
    d_alpha2[p] = ex;
    atomicAdd(&d_s2[d], ex);
}

// ------------------- CSR gather (no atomics) ----------------------------------
__global__ void gather1(const float* __restrict__ bias) {
    int d = blockIdx.x;
    int t = threadIdx.x;          // 256, channel
    int h = t >> 6;
    __shared__ float sh_sinv[4];
    __shared__ int   sh_src[32];
    __shared__ float sh_w[32 * 4];
    if (t < 4) sh_sinv[t] = 1.0f / d_s1[d * 4 + t];
    int r0 = d_rowptr[d], r1 = d_rowptr[d + 1];
    __syncthreads();
    float sinv = sh_sinv[h];
    float acc = 0.f;
    for (int p0 = r0; p0 < r1; p0 += 32) {
        int m = min(32, r1 - p0);
        __syncthreads();
        if (t < m * 4) sh_w[t] = d_alpha1[(size_t)p0 * 4 + t];
        if (t < m)     sh_src[t] = d_esrc[p0 + t];
        __syncthreads();
        for (int j = 0; j < m; j++)
            acc += sh_w[j * 4 + h] * d_xs1[(size_t)sh_src[j] * C1 + t];
    }
    d_out1[(size_t)d * C1 + t] = acc * sinv + bias[t];
}
__global__ void gather2(const float* __restrict__ bias) {
    int d = blockIdx.x;
    int t = threadIdx.x;          // 64
    __shared__ int   sh_src[64];
    __shared__ float sh_w[64];
    int r0 = d_rowptr[d], r1 = d_rowptr[d + 1];
    float sinv = 1.0f / d_s2[d];
    float acc = 0.f;
    for (int p0 = r0; p0 < r1; p0 += 64) {
        int m = min(64, r1 - p0);
        __syncthreads();
        if (t < m) {
            sh_w[t]   = d_alpha2[p0 + t];
            sh_src[t] = d_esrc[p0 + t];
        }
        __syncthreads();
        for (int j = 0; j < m; j++)
            acc += sh_w[j] * d_xs2[(size_t)sh_src[j] * HID + t];
    }
    d_out2[(size_t)d * HID + t] = acc * sinv + bias[t];
}

// ------------------- batchnorm -------------------------------------------------
__global__ void bn_stats(const float* __restrict__ X, int C) {
    int t = threadIdx.x;
    int rows_per = (NN + gridDim.x - 1) / gridDim.x;
    int r0 = blockIdx.x * rows_per;
    int r1 = r0 + rows_per; if (r1 > NN) r1 = NN;
    float s = 0.f, q = 0.f;
    for (int r = r0; r < r1; r++) {
        float v = X[(size_t)r * C + t];
        s += v;
        q += v * v;
    }
    atomicAdd(&d_colsum[t], s);
    atomicAdd(&d_colsq[t], q);
}
__global__ void bn_apply_relu(float* X, const float* __restrict__ g,
                              const float* __restrict__ b, int C, int total) {
    int idx = blockIdx.x * blockDim.x + threadIdx.x;
    if (idx >= total) return;
    int t = idx % C;
    float mu = d_colsum[t] / (float)NN;
    float var = d_colsq[t] / (float)NN - mu * mu;
    float y = (X[idx] - mu) * rsqrtf(var + EPS) * g[t] + b[t];
    X[idx] = y > 0.f ? y : 0.f;
}

// ------------------- pooling ----------------------------------------------------
__global__ void gate_kernel(const float* __restrict__ Wg, const float* __restrict__ bg,
                            const int* __restrict__ batch) {
    int n = blockIdx.x * blockDim.x + threadIdx.x;
    if (n >= NN) return;
    const float* xr = d_out2 + (size_t)n * HID;
    float s = bg[0];
#pragma unroll
    for (int f = 0; f < HID; f++) s += xr[f] * Wg[f];
    d_gate[n] = s;
    atomicMax(&d_gm[batch[n]], fenc(s));
}
__global__ void gate_exp_sum(const int* __restrict__ batch) {
    int n = blockIdx.x * blockDim.x + threadIdx.x;
    if (n >= NN) return;
    int b = batch[n];
    float ex = expf(d_gate[n] - fdec(d_gm[b]));
    d_gate[n] = ex;
    atomicAdd(&d_gs[b], ex);
}
__global__ void pool_scatter(const int* __restrict__ batch, float* __restrict__ out) {
    int idx = blockIdx.x * blockDim.x + threadIdx.x;
    if (idx >= NN * HID) return;
    int n = idx >> 6, c = idx & 63;
    int b = batch[n];
    float w = d_gate[n] / d_gs[b];
    atomicAdd(&out[b * HID + c], d_out2[(size_t)n * HID + c] * w);
}

// ------------------- launch ------------------------------------------------------
static inline int gdiv(long long a, int b) { return (int)((a + b - 1) / b); }

extern "C" void kernel_launch(void* const* d_in, const int* in_sizes, int n_in,
                              void* d_out, int out_size) {
    const float* x     = (const float*)d_in[0];
    const float* ea    = (const float*)d_in[1];
    const int*   ei    = (const int*)d_in[2];
    const int*   batch = (const int*)d_in[3];
    const float* W1    = (const float*)d_in[4];
    const float* We1   = (const float*)d_in[5];
    const float* as1   = (const float*)d_in[6];
    const float* ad1   = (const float*)d_in[7];
    const float* ae1   = (const float*)d_in[8];
    const float* b1    = (const float*)d_in[9];
    const float* g1    = (const float*)d_in[10];
    const float* bb1   = (const float*)d_in[11];
    const float* W2    = (const float*)d_in[12];
    const float* We2   = (const float*)d_in[13];
    const float* as2   = (const float*)d_in[14];
    const float* ad2   = (const float*)d_in[15];
    const float* ae2   = (const float*)d_in[16];
    const float* b2    = (const float*)d_in[17];
    const float* g2    = (const float*)d_in[18];
    const float* bb2   = (const float*)d_in[19];
    const float* Wg    = (const float*)d_in[20];
    const float* bg    = (const float*)d_in[21];
    float* out = (float*)d_out;

    const int* src = ei;
    const int* dst = ei + EE;

    int*      p_deg;    cudaGetSymbolAddress((void**)&p_deg, d_deg);
    int*      p_cursor; cudaGetSymbolAddress((void**)&p_cursor, d_cursor);
    unsigned* p_m1;     cudaGetSymbolAddress((void**)&p_m1, d_m1);
    float*    p_s1;     cudaGetSymbolAddress((void**)&p_s1, d_s1);
    unsigned* p_m2;     cudaGetSymbolAddress((void**)&p_m2, d_m2);
    float*    p_s2;     cudaGetSymbolAddress((void**)&p_s2, d_s2);
    float*    p_colsum; cudaGetSymbolAddress((void**)&p_colsum, d_colsum);
    float*    p_colsq;  cudaGetSymbolAddress((void**)&p_colsq, d_colsq);
    unsigned* p_gm;     cudaGetSymbolAddress((void**)&p_gm, d_gm);
    float*    p_gs;     cudaGetSymbolAddress((void**)&p_gs, d_gs);
    float*    p_xs1;    cudaGetSymbolAddress((void**)&p_xs1, d_xs1);
    float*    p_out1;   cudaGetSymbolAddress((void**)&p_out1, d_out1);
    float*    p_xs2;    cudaGetSymbolAddress((void**)&p_xs2, d_xs2);
    float*    p_out2;   cudaGetSymbolAddress((void**)&p_out2, d_out2);

    // ---- init ----
    fill_i<<<gdiv(NN, 256), 256>>>(p_deg, 1, NN);          // self loop
    fill_i<<<gdiv(NN, 256), 256>>>(p_cursor, 0, NN);
    fill_u<<<gdiv(NN * 4, 256), 256>>>(p_m1, 0u, NN * 4);
    fill_f<<<gdiv(NN * 4, 256), 256>>>(p_s1, 0.f, NN * 4);
    fill_u<<<gdiv(NN, 256), 256>>>(p_m2, 0u, NN);
    fill_f<<<gdiv(NN, 256), 256>>>(p_s2, 0.f, NN);
    fill_f<<<1, 256>>>(p_colsum, 0.f, C1);
    fill_f<<<1, 256>>>(p_colsq, 0.f, C1);
    fill_u<<<1, 64>>>(p_gm, 0u, BB);
    fill_f<<<1, 64>>>(p_gs, 0.f, BB);
    fill_f<<<gdiv(BB * HID, 256), 256>>>(out, 0.f, BB * HID);

    // ---- CSR build ----
    hist_kernel<<<gdiv(EE, 256), 256>>>(dst);
    scan_kernel<<<1, 1024>>>();
    csr_fill<<<gdiv(ET, 256), 256>>>(src, dst);

    // ---- self-loop mean edge attrs ----
    ea_mean_csr<<<gdiv(NN * 32, 256), 256>>>(ea);

    // ---- layer 1 ----
    {
        dim3 g(C1 / 64, gdiv(NN, 64));
        gemm_rt<<<g, 256>>>(x, W1, p_xs1, NN, FIN, C1);
    }
    al_kernel1<<<gdiv(NN * 4, 256), 256>>>(as1, ad1);
    c1_kernel<<<1, 128>>>(We1, ae1);
    edge_alpha1<<<gdiv(ET, 256), 256>>>(ea, src, dst);
    exp_sum1<<<gdiv((long long)ET * 4, 256), 256>>>();
    gather1<<<NN, 256>>>(b1);
    bn_stats<<<128, C1>>>(p_out1, C1);
    bn_apply_relu<<<gdiv(NN * C1, 256), 256>>>(p_out1, g1, bb1, C1, NN * C1);

    // ---- layer 2 ----
    {
        dim3 g(HID / 64, gdiv(NN, 64));
        gemm_rt<<<g, 256>>>(p_out1, W2, p_xs2, NN, C1, HID);
    }
    al_kernel2<<<gdiv(NN, 256), 256>>>(as2, ad2);
    c2_kernel<<<1, 32>>>(We2, ae2);
    edge_alpha2<<<gdiv(ET, 256), 256>>>(ea, src, dst);
    exp_sum2<<<gdiv(ET, 256), 256>>>();
    gather2<<<NN, 64>>>(b2);
    fill_f<<<1, 64>>>(p_colsum, 0.f, HID);
    fill_f<<<1, 64>>>(p_colsq, 0.f, HID);
    bn_stats<<<128, HID>>>(p_out2, HID);
    bn_apply_relu<<<gdiv(NN * HID, 256), 256>>>(p_out2, g2, bb2, HID, NN * HID);

    // ---- pooling ----
    gate_kernel<<<gdiv(NN, 256), 256>>>(Wg, bg, batch);
    gate_exp_sum<<<gdiv(NN, 256), 256>>>(batch);
    pool_scatter<<<gdiv(NN * HID, 256), 256>>>(batch, out);
}

// round 5
// speedup vs baseline: 3.0186x; 1.0601x over previous
#include <cuda_runtime.h>

#define NN 30000
#define EE 480000
#define ET (EE + NN)   // edges incl. self loops
#define BB 64
#define FIN 128
#define HID 64
#define ED 32
#define C1 256         // 4*HID
#define NEG 0.2f
#define EPS 1e-5f

typedef unsigned long long ull;

// ------------------- scratch -------------------------------------------------
__device__ int      d_deg[NN];
__device__ int      d_rowptr[NN + 1];
__device__ int      d_cursor[NN];
__device__ int      d_esrc[ET];
__device__ int      d_eid[ET];
__device__ int      d_edst[ET];
__device__ int      d_pos[ET];

__device__ float    d_mean_ea[NN * ED];
__device__ float    d_xs1[(size_t)NN * C1];
__device__ float    d_als1[NN * 4];
__device__ float    d_ald1[NN * 4];
__device__ float    d_c1[ED * 4];
__device__ float    d_alpha1[(size_t)ET * 4];   // CSR-ordered
__device__ unsigned d_m1[NN * 4];
__device__ float    d_s1[NN * 4];
__device__ float    d_out1[(size_t)NN * C1];
__device__ float    d_colsum1[C1];
__device__ float    d_colsq1[C1];
__device__ float    d_colsum2[HID];
__device__ float    d_colsq2[HID];
__device__ float    d_xs2[(size_t)NN * HID];
__device__ float    d_als2[NN];
__device__ float    d_ald2[NN];
__device__ float    d_c2[ED];
__device__ float    d_alpha2[ET];               // CSR-ordered
__device__ unsigned d_m2[NN];
__device__ float    d_s2[NN];
__device__ float    d_out2[(size_t)NN * HID];
__device__ float    d_gate[NN];
__device__ unsigned d_gm[BB];
__device__ float    d_gs[BB];

// ------------------- helpers -------------------------------------------------
__device__ __forceinline__ unsigned fenc(float f) {
    unsigned u = __float_as_uint(f);
    return (u & 0x80000000u) ? ~u : (u | 0x80000000u);
}
__device__ __forceinline__ float fdec(unsigned u) {
    return (u & 0x80000000u) ? __uint_as_float(u & 0x7FFFFFFFu) : __uint_as_float(~u);
}
__device__ __forceinline__ ull pack2(float lo, float hi) {
    ull r;
    asm("mov.b64 %0, {%1, %2};" : "=l"(r) : "f"(lo), "f"(hi));
    return r;
}
__device__ __forceinline__ void unpack2(ull v, float& lo, float& hi) {
    asm("mov.b64 {%0, %1}, %2;" : "=f"(lo), "=f"(hi) : "l"(v));
}
__device__ __forceinline__ void fma2(ull& acc, ull a, ull b) {
    asm("fma.rn.f32x2 %0, %1, %2, %0;" : "+l"(acc) : "l"(a), "l"(b));
}

// ------------------- fused init ----------------------------------------------
__global__ void init_all(float* out) {
    int i = blockIdx.x * blockDim.x + threadIdx.x;
    if (i < NN * 4) { d_m1[i] = 0u; d_s1[i] = 0.f; }
    if (i < NN) { d_m2[i] = 0u; d_s2[i] = 0.f; d_deg[i] = 1; d_cursor[i] = 0; }
    if (i < C1) { d_colsum1[i] = 0.f; d_colsq1[i] = 0.f; }
    if (i < HID) { d_colsum2[i] = 0.f; d_colsq2[i] = 0.f; }
    if (i < BB) { d_gm[i] = 0u; d_gs[i] = 0.f; }
    if (i < BB * HID) out[i] = 0.f;
}

// ------------------- CSR build -----------------------------------------------
__global__ void hist_kernel(const int* __restrict__ dst) {
    int e = blockIdx.x * blockDim.x + threadIdx.x;
    if (e < EE) atomicAdd(&d_deg[dst[e]], 1);
}

__global__ void scan_kernel() {
    __shared__ int wsum[32];
    const int PER = 30;
    int t = threadIdx.x;
    int base = t * PER;
    int vals[PER];
    int s = 0;
#pragma unroll
    for (int i = 0; i < PER; i++) {
        int idx = base + i;
        vals[i] = (idx < NN) ? d_deg[idx] : 0;
        s += vals[i];
    }
    int lane = t & 31, w = t >> 5;
    int x = s;
#pragma unroll
    for (int off = 1; off < 32; off <<= 1) {
        int y = __shfl_up_sync(0xFFFFFFFFu, x, off);
        if (lane >= off) x += y;
    }
    if (lane == 31) wsum[w] = x;
    __syncthreads();
    if (w == 0) {
        int y = wsum[lane];
#pragma unroll
        for (int off = 1; off < 32; off <<= 1) {
            int z = __shfl_up_sync(0xFFFFFFFFu, y, off);
            if (lane >= off) y += z;
        }
        wsum[lane] = y;
    }
    __syncthreads();
    int excl = x - s + (w > 0 ? wsum[w - 1] : 0);
    int run = excl;
#pragma unroll
    for (int i = 0; i < PER; i++) {
        int idx = base + i;
        if (idx < NN) d_rowptr[idx] = run;
        run += vals[i];
    }
    if (t == 0) d_rowptr[NN] = ET;
}

__global__ void csr_fill(const int* __restrict__ src, const int* __restrict__ dst) {
    int e = blockIdx.x * blockDim.x + threadIdx.x;
    if (e >= ET) return;
    int s, d;
    if (e < EE) { s = src[e]; d = dst[e]; }
    else        { s = d = e - EE; }
    int p = d_rowptr[d] + atomicAdd(&d_cursor[d], 1);
    d_esrc[p] = s;
    d_eid[p]  = e;
    d_edst[p] = d;
    d_pos[e]  = p;
}

// ------------------- self-loop mean edge attr (CSR gather) -------------------
__global__ void ea_mean_csr(const float* __restrict__ ea) {
    int warp = (blockIdx.x * blockDim.x + threadIdx.x) >> 5;
    int lane = threadIdx.x & 31;
    if (warp >= NN) return;
    int r0 = d_rowptr[warp], r1 = d_rowptr[warp + 1];
    float s = 0.f;
    int cnt = 0;
    for (int p = r0; p < r1; p++) {
        int e = d_eid[p];
        if (e < EE) { s += ea[(size_t)e * ED + lane]; cnt++; }
    }
    d_mean_ea[warp * ED + lane] = s / (float)(cnt > 1 ? cnt : 1);
}

// ------------------- f32x2 GEMM: C[M,N] = A[M,K] x B[K,N] --------------------
// BM=128, BN=64, BK=16, 256 threads, 8x4 per thread (rows paired for f32x2).
__global__ void __launch_bounds__(256) gemm_f32x2(
    const float* __restrict__ A, const float* __restrict__ B,
    float* __restrict__ C, int M, int K, int N) {
    const int BM = 128, BN = 64, BK = 16;
    __shared__ float As[BK][BM + 4];   // [k][m]; row stride 132 floats (16B-aligned)
    __shared__ float Bs[BK][BN];
    int tid = threadIdx.x;
    int tx = tid & 15, ty = tid >> 4;
    int m0 = blockIdx.y * BM, n0 = blockIdx.x * BN;

    ull acc[4][4];
#pragma unroll
    for (int i = 0; i < 4; i++)
#pragma unroll
        for (int j = 0; j < 4; j++) acc[i][j] = 0ull;

    int ar = tid >> 1;              // 0..127 row within tile
    int akb = (tid & 1) * 8;        // k offset 0 or 8
    int gr_a = m0 + ar;
    int br = tid >> 4;              // 0..15 k row for B
    int bc = (tid & 15) * 4;        // col within tile

    for (int k0 = 0; k0 < K; k0 += BK) {
        // load A tile (transposed into As[k][m])
        float4 a4a, a4b;
        if (gr_a < M) {
            a4a = *(const float4*)&A[(size_t)gr_a * K + k0 + akb];
            a4b = *(const float4*)&A[(size_t)gr_a * K + k0 + akb + 4];
        } else {
            a4a = make_float4(0.f, 0.f, 0.f, 0.f);
            a4b = a4a;
        }
        As[akb + 0][ar] = a4a.x; As[akb + 1][ar] = a4a.y;
        As[akb + 2][ar] = a4a.z; As[akb + 3][ar] = a4a.w;
        As[akb + 4][ar] = a4b.x; As[akb + 5][ar] = a4b.y;
        As[akb + 6][ar] = a4b.z; As[akb + 7][ar] = a4b.w;
        // load B tile
        *(float4*)&Bs[br][bc] = *(const float4*)&B[(size_t)(k0 + br) * N + n0 + bc];
        __syncthreads();
#pragma unroll
        for (int kk = 0; kk < BK; kk++) {
            ulonglong2 ap01 = *(const ulonglong2*)&As[kk][ty * 8];
            ulonglong2 ap23 = *(const ulonglong2*)&As[kk][ty * 8 + 4];
            float4 bq = *(const float4*)&Bs[kk][tx * 4];
            ull bb0 = pack2(bq.x, bq.x);
            ull bb1 = pack2(bq.y, bq.y);
            ull bb2 = pack2(bq.z, bq.z);
            ull bb3 = pack2(bq.w, bq.w);
            ull ap[4] = {ap01.x, ap01.y, ap23.x, ap23.y};
#pragma unroll
            for (int i = 0; i < 4; i++) {
                fma2(acc[i][0], ap[i], bb0);
                fma2(acc[i][1], ap[i], bb1);
                fma2(acc[i][2], ap[i], bb2);
                fma2(acc[i][3], ap[i], bb3);
            }
        }
        __syncthreads();
    }
    // store: row pair i -> rows m0+ty*8+2i, +2i+1 ; cols n0+tx*4..+3
#pragma unroll
    for (int i = 0; i < 4; i++) {
        float lo0, hi0, lo1, hi1, lo2, hi2, lo3, hi3;
        unpack2(acc[i][0], lo0, hi0);
        unpack2(acc[i][1], lo1, hi1);
        unpack2(acc[i][2], lo2, hi2);
        unpack2(acc[i][3], lo3, hi3);
        int r0 = m0 + ty * 8 + 2 * i;
        if (r0 < M)
            *(float4*)&C[(size_t)r0 * N + n0 + tx * 4] = make_float4(lo0, lo1, lo2, lo3);
        if (r0 + 1 < M)
            *(float4*)&C[(size_t)(r0 + 1) * N + n0 + tx * 4] = make_float4(hi0, hi1, hi2, hi3);
    }
}

// ------------------- attention logits ----------------------------------------
__global__ void al_kernel1(const float* __restrict__ as, const float* __restrict__ ad) {
    int idx = blockIdx.x * blockDim.x + threadIdx.x;
    if (idx >= NN * 4) return;
    int n = idx >> 2, h = idx & 3;
    const float* xr = d_xs1 + (size_t)n * C1 + h * HID;
    float s = 0.f, d = 0.f;
#pragma unroll
    for (int f = 0; f < HID; f++) {
        float v = xr[f];
        s += v * as[h * HID + f];
        d += v * ad[h * HID + f];
    }
    d_als1[idx] = s;
    d_ald1[idx] = d;
}
__global__ void al_kernel2(const float* __restrict__ as, const float* __restrict__ ad) {
    int n = blockIdx.x * blockDim.x + threadIdx.x;
    if (n >= NN) return;
    const float* xr = d_xs2 + (size_t)n * HID;
    float s = 0.f, d = 0.f;
#pragma unroll
    for (int f = 0; f < HID; f++) {
        float v = xr[f];
        s += v * as[f];
        d += v * ad[f];
    }
    d_als2[n] = s;
    d_ald2[n] = d;
}

__global__ void c1_kernel(const float* __restrict__ We1, const float* __restrict__ ae1) {
    int idx = threadIdx.x;
    if (idx >= ED * 4) return;
    int k = idx >> 2, h = idx & 3;
    float s = 0.f;
#pragma unroll
    for (int f = 0; f < HID; f++) s += We1[k * C1 + h * HID + f] * ae1[h * HID + f];
    d_c1[k * 4 + h] = s;
}
__global__ void c2_kernel(const float* __restrict__ We2, const float* __restrict__ ae2) {
    int k = threadIdx.x;
    if (k >= ED) return;
    float s = 0.f;
#pragma unroll
    for (int f = 0; f < HID; f++) s += We2[k * HID + f] * ae2[f];
    d_c2[k] = s;
}

// ------------------- edge alpha (writes CSR-ordered) ---------------------------
__global__ void edge_alpha1(const float* __restrict__ ea, const int* __restrict__ src,
                            const int* __restrict__ dst) {
    int e = blockIdx.x * blockDim.x + threadIdx.x;
    if (e >= ET) return;
    int s, d;
    const float* row;
    if (e < EE) { s = src[e]; d = dst[e]; row = ea + (size_t)e * ED; }
    else        { s = d = e - EE; row = d_mean_ea + (size_t)(e - EE) * ED; }
    float ec0 = 0.f, ec1 = 0.f, ec2 = 0.f, ec3 = 0.f;
#pragma unroll
    for (int k = 0; k < ED; k++) {
        float v = __ldg(row + k);
        ec0 += v * d_c1[k * 4 + 0];
        ec1 += v * d_c1[k * 4 + 1];
        ec2 += v * d_c1[k * 4 + 2];
        ec3 += v * d_c1[k * 4 + 3];
    }
    float ec[4] = {ec0, ec1, ec2, ec3};
    size_t pb = (size_t)d_pos[e] * 4;
#pragma unroll
    for (int h = 0; h < 4; h++) {
        float a = d_als1[s * 4 + h] + d_ald1[d * 4 + h] + ec[h];
        a = a > 0.f ? a : NEG * a;
        d_alpha1[pb + h] = a;
        atomicMax(&d_m1[d * 4 + h], fenc(a));
    }
}
__global__ void exp_sum1() {
    int p = blockIdx.x * blockDim.x + threadIdx.x;
    if (p >= ET) return;
    int d = d_edst[p];
    float4 a = *(float4*)&d_alpha1[(size_t)p * 4];
    const unsigned* mr = &d_m1[d * 4];
    a.x = expf(a.x - fdec(mr[0]));
    a.y = expf(a.y - fdec(mr[1]));
    a.z = expf(a.z - fdec(mr[2]));
    a.w = expf(a.w - fdec(mr[3]));
    *(float4*)&d_alpha1[(size_t)p * 4] = a;
    atomicAdd(&d_s1[d * 4 + 0], a.x);
    atomicAdd(&d_s1[d * 4 + 1], a.y);
    atomicAdd(&d_s1[d * 4 + 2], a.z);
    atomicAdd(&d_s1[d * 4 + 3], a.w);
}
__global__ void edge_alpha2(const float* __restrict__ ea, const int* __restrict__ src,
                            const int* __restrict__ dst) {
    int e = blockIdx.x * blockDim.x + threadIdx.x;
    if (e >= ET) return;
    int s, d;
    const float* row;
    if (e < EE) { s = src[e]; d = dst[e]; row = ea + (size_t)e * ED; }
    else        { s = d = e - EE; row = d_mean_ea + (size_t)(e - EE) * ED; }
    float ec = 0.f;
#pragma unroll
    for (int k = 0; k < ED; k++) ec += __ldg(row + k) * d_c2[k];
    float a = d_als2[s] + d_ald2[d] + ec;
    a = a > 0.f ? a : NEG * a;
    d_alpha2[d_pos[e]] = a;
    atomicMax(&d_m2[d], fenc(a));
}
__global__ void exp_sum2() {
    int p = blockIdx.x * blockDim.x + threadIdx.x;
    if (p >= ET) return;
    int d = d_edst[p];
    float ex = expf(d_alpha2[p] - fdec(d_m2[d]));
    d_alpha2[p] = ex;
    atomicAdd(&d_s2[d], ex);
}

// ------------------- CSR gather (no atomics) ----------------------------------
__global__ void gather1(const float* __restrict__ bias) {
    int d = blockIdx.x;
    int t = threadIdx.x;          // 256, channel
    int h = t >> 6;
    __shared__ float sh_sinv[4];
    __shared__ int   sh_src[32];
    __shared__ float sh_w[32 * 4];
    if (t < 4) sh_sinv[t] = 1.0f / d_s1[d * 4 + t];
    int r0 = d_rowptr[d], r1 = d_rowptr[d + 1];
    __syncthreads();
    float sinv = sh_sinv[h];
    float acc = 0.f;
    for (int p0 = r0; p0 < r1; p0 += 32) {
        int m = min(32, r1 - p0);
        __syncthreads();
        if (t < m * 4) sh_w[t] = d_alpha1[(size_t)p0 * 4 + t];
        if (t < m)     sh_src[t] = d_esrc[p0 + t];
        __syncthreads();
        for (int j = 0; j < m; j++)
            acc += sh_w[j * 4 + h] * d_xs1[(size_t)sh_src[j] * C1 + t];
    }
    d_out1[(size_t)d * C1 + t] = acc * sinv + bias[t];
}
__global__ void gather2(const float* __restrict__ bias) {
    int d = blockIdx.x;
    int t = threadIdx.x;          // 64
    __shared__ int   sh_src[64];
    __shared__ float sh_w[64];
    int r0 = d_rowptr[d], r1 = d_rowptr[d + 1];
    float sinv = 1.0f / d_s2[d];
    float acc = 0.f;
    for (int p0 = r0; p0 < r1; p0 += 64) {
        int m = min(64, r1 - p0);
        __syncthreads();
        if (t < m) {
            sh_w[t]   = d_alpha2[p0 + t];
            sh_src[t] = d_esrc[p0 + t];
        }
        __syncthreads();
        for (int j = 0; j < m; j++)
            acc += sh_w[j] * d_xs2[(size_t)sh_src[j] * HID + t];
    }
    d_out2[(size_t)d * HID + t] = acc * sinv + bias[t];
}

// ------------------- batchnorm -------------------------------------------------
__global__ void bn_stats(const float* __restrict__ X, float* sum, float* sq, int C) {
    int t = threadIdx.x;
    int rows_per = (NN + gridDim.x - 1) / gridDim.x;
    int r0 = blockIdx.x * rows_per;
    int r1 = r0 + rows_per; if (r1 > NN) r1 = NN;
    float s = 0.f, q = 0.f;
    for (int r = r0; r < r1; r++) {
        float v = X[(size_t)r * C + t];
        s += v;
        q += v * v;
    }
    atomicAdd(&sum[t], s);
    atomicAdd(&sq[t], q);
}
__global__ void bn_apply_relu(float* X, const float* __restrict__ sum,
                              const float* __restrict__ sq,
                              const float* __restrict__ g,
                              const float* __restrict__ b, int C, int total) {
    int idx = blockIdx.x * blockDim.x + threadIdx.x;
    if (idx >= total) return;
    int t = idx % C;
    float mu = sum[t] / (float)NN;
    float var = sq[t] / (float)NN - mu * mu;
    float y = (X[idx] - mu) * rsqrtf(var + EPS) * g[t] + b[t];
    X[idx] = y > 0.f ? y : 0.f;
}

// ------------------- pooling ----------------------------------------------------
__global__ void gate_kernel(const float* __restrict__ Wg, const float* __restrict__ bg,
                            const int* __restrict__ batch) {
    int n = blockIdx.x * blockDim.x + threadIdx.x;
    if (n >= NN) return;
    const float* xr = d_out2 + (size_t)n * HID;
    float s = bg[0];
#pragma unroll
    for (int f = 0; f < HID; f++) s += xr[f] * Wg[f];
    d_gate[n] = s;
    atomicMax(&d_gm[batch[n]], fenc(s));
}
__global__ void gate_exp_sum(const int* __restrict__ batch) {
    int n = blockIdx.x * blockDim.x + threadIdx.x;
    if (n >= NN) return;
    int b = batch[n];
    float ex = expf(d_gate[n] - fdec(d_gm[b]));
    d_gate[n] = ex;
    atomicAdd(&d_gs[b], ex);
}
__global__ void pool_scatter(const int* __restrict__ batch, float* __restrict__ out) {
    int idx = blockIdx.x * blockDim.x + threadIdx.x;
    if (idx >= NN * HID) return;
    int n = idx >> 6, c = idx & 63;
    int b = batch[n];
    float w = d_gate[n] / d_gs[b];
    atomicAdd(&out[b * HID + c], d_out2[(size_t)n * HID + c] * w);
}

// ------------------- launch ------------------------------------------------------
static inline int gdiv(long long a, int b) { return (int)((a + b - 1) / b); }

extern "C" void kernel_launch(void* const* d_in, const int* in_sizes, int n_in,
                              void* d_out, int out_size) {
    const float* x     = (const float*)d_in[0];
    const float* ea    = (const float*)d_in[1];
    const int*   ei    = (const int*)d_in[2];
    const int*   batch = (const int*)d_in[3];
    const float* W1    = (const float*)d_in[4];
    const float* We1   = (const float*)d_in[5];
    const float* as1   = (const float*)d_in[6];
    const float* ad1   = (const float*)d_in[7];
    const float* ae1   = (const float*)d_in[8];
    const float* b1    = (const float*)d_in[9];
    const float* g1    = (const float*)d_in[10];
    const float* bb1   = (const float*)d_in[11];
    const float* W2    = (const float*)d_in[12];
    const float* We2   = (const float*)d_in[13];
    const float* as2   = (const float*)d_in[14];
    const float* ad2   = (const float*)d_in[15];
    const float* ae2   = (const float*)d_in[16];
    const float* b2    = (const float*)d_in[17];
    const float* g2    = (const float*)d_in[18];
    const float* bb2   = (const float*)d_in[19];
    const float* Wg    = (const float*)d_in[20];
    const float* bg    = (const float*)d_in[21];
    float* out = (float*)d_out;

    const int* src = ei;
    const int* dst = ei + EE;

    float* p_xs1;     cudaGetSymbolAddress((void**)&p_xs1, d_xs1);
    float* p_out1;    cudaGetSymbolAddress((void**)&p_out1, d_out1);
    float* p_xs2;     cudaGetSymbolAddress((void**)&p_xs2, d_xs2);
    float* p_out2;    cudaGetSymbolAddress((void**)&p_out2, d_out2);
    float* p_colsum1; cudaGetSymbolAddress((void**)&p_colsum1, d_colsum1);
    float* p_colsq1;  cudaGetSymbolAddress((void**)&p_colsq1, d_colsq1);
    float* p_colsum2; cudaGetSymbolAddress((void**)&p_colsum2, d_colsum2);
    float* p_colsq2;  cudaGetSymbolAddress((void**)&p_colsq2, d_colsq2);

    // ---- init (single fused kernel) ----
    init_all<<<gdiv(NN * 4, 256), 256>>>(out);

    // ---- CSR build ----
    hist_kernel<<<gdiv(EE, 256), 256>>>(dst);
    scan_kernel<<<1, 1024>>>();
    csr_fill<<<gdiv(ET, 256), 256>>>(src, dst);

    // ---- self-loop mean edge attrs ----
    ea_mean_csr<<<gdiv(NN * 32, 256), 256>>>(ea);

    // ---- layer 1 ----
    {
        dim3 g(C1 / 64, gdiv(NN, 128));
        gemm_f32x2<<<g, 256>>>(x, W1, p_xs1, NN, FIN, C1);
    }
    al_kernel1<<<gdiv(NN * 4, 256), 256>>>(as1, ad1);
    c1_kernel<<<1, 128>>>(We1, ae1);
    edge_alpha1<<<gdiv(ET, 256), 256>>>(ea, src, dst);
    exp_sum1<<<gdiv(ET, 256), 256>>>();
    gather1<<<NN, 256>>>(b1);
    bn_stats<<<128, C1>>>(p_out1, p_colsum1, p_colsq1, C1);
    bn_apply_relu<<<gdiv(NN * C1, 256), 256>>>(p_out1, p_colsum1, p_colsq1, g1, bb1, C1, NN * C1);

    // ---- layer 2 ----
    {
        dim3 g(HID / 64, gdiv(NN, 128));
        gemm_f32x2<<<g, 256>>>(p_out1, W2, p_xs2, NN, C1, HID);
    }
    al_kernel2<<<gdiv(NN, 256), 256>>>(as2, ad2);
    c2_kernel<<<1, 32>>>(We2, ae2);
    edge_alpha2<<<gdiv(ET, 256), 256>>>(ea, src, dst);
    exp_sum2<<<gdiv(ET, 256), 256>>>();
    gather2<<<NN, 64>>>(b2);
    bn_stats<<<128, HID>>>(p_out2, p_colsum2, p_colsq2, HID);
    bn_apply_relu<<<gdiv(NN * HID, 256), 256>>>(p_out2, p_colsum2, p_colsq2, g2, bb2, HID, NN * HID);

    // ---- pooling ----
    gate_kernel<<<gdiv(NN, 256), 256>>>(Wg, bg, batch);
    gate_exp_sum<<<gdiv(NN, 256), 256>>>(batch);
    pool_scatter<<<gdiv(NN * HID, 256), 256>>>(batch, out);
}

// round 6
// speedup vs baseline: 3.9500x; 1.3086x over previous
#include <cuda_runtime.h>

#define NN 30000
#define EE 480000
#define ET (EE + NN)
#define BB 64
#define FIN 128
#define HID 64
#define ED 32
#define C1 256
#define NEG 0.2f
#define EPS 1e-5f

typedef unsigned long long ull;

// ------------------- scratch -------------------------------------------------
__device__ int      d_deg[NN];
__device__ int      d_rowptr[NN + 1];
__device__ int      d_cursor[NN];
__device__ int      d_esrc[ET];
__device__ int      d_eid[ET];
__device__ int      d_edst[ET];
__device__ int      d_pos[ET];

__device__ float    d_mean_ea[NN * ED];
__device__ float    d_vs1[512];         // [h*128+k]
__device__ float    d_vd1[512];
__device__ float    d_c1[ED * 4];
__device__ float    d_c2[ED];
__device__ float    d_als1[NN * 4];
__device__ float    d_ald1[NN * 4];
__device__ float    d_alpha1[(size_t)ET * 4];   // CSR order, raw lrelu logits
__device__ float    d_ec2[ET];                  // CSR order, ea . c2
__device__ unsigned d_m1[NN * 4];
__device__ float    d_tmp[(size_t)NN * 512];    // [n][h*128+k] aggregated x
__device__ float    d_out1[(size_t)NN * C1];
__device__ float    d_colsum1[C1];
__device__ float    d_colsq1[C1];
__device__ float    d_xs2[(size_t)NN * HID];
__device__ float    d_als2[NN];
__device__ float    d_ald2[NN];
__device__ float    d_alpha2[ET];               // CSR order
__device__ unsigned d_m2[NN];
__device__ float    d_out2[(size_t)NN * HID];
__device__ float    d_colsum2[HID];
__device__ float    d_colsq2[HID];
__device__ float    d_gate[NN];

// ------------------- helpers -------------------------------------------------
__device__ __forceinline__ unsigned fenc(float f) {
    unsigned u = __float_as_uint(f);
    return (u & 0x80000000u) ? ~u : (u | 0x80000000u);
}
__device__ __forceinline__ float fdec(unsigned u) {
    return (u & 0x80000000u) ? __uint_as_float(u & 0x7FFFFFFFu) : __uint_as_float(~u);
}
__device__ __forceinline__ ull pack2(float lo, float hi) {
    ull r;
    asm("mov.b64 %0, {%1, %2};" : "=l"(r) : "f"(lo), "f"(hi));
    return r;
}
__device__ __forceinline__ void unpack2(ull v, float& lo, float& hi) {
    asm("mov.b64 {%0, %1}, %2;" : "=f"(lo), "=f"(hi) : "l"(v));
}
__device__ __forceinline__ void fma2(ull& acc, ull a, ull b) {
    asm("fma.rn.f32x2 %0, %1, %2, %0;" : "+l"(acc) : "l"(a), "l"(b));
}

// ------------------- init ------------------------------------------------------
__global__ void init_all() {
    int i = blockIdx.x * blockDim.x + threadIdx.x;
    if (i < NN * 4) d_m1[i] = 0u;
    if (i < NN) { d_m2[i] = 0u; d_deg[i] = 1; d_cursor[i] = 0; }
    if (i < C1) { d_colsum1[i] = 0.f; d_colsq1[i] = 0.f; }
    if (i < HID) { d_colsum2[i] = 0.f; d_colsq2[i] = 0.f; }
}

// ------------------- CSR build --------------------------------------------------
__global__ void hist_kernel(const int* __restrict__ dst) {
    int e = blockIdx.x * blockDim.x + threadIdx.x;
    if (e < EE) atomicAdd(&d_deg[dst[e]], 1);
}

__global__ void scan_kernel() {
    __shared__ int wsum[32];
    const int PER = 30;
    int t = threadIdx.x;
    int base = t * PER;
    int vals[PER];
    int s = 0;
#pragma unroll
    for (int i = 0; i < PER; i++) {
        int idx = base + i;
        vals[i] = (idx < NN) ? d_deg[idx] : 0;
        s += vals[i];
    }
    int lane = t & 31, w = t >> 5;
    int x = s;
#pragma unroll
    for (int off = 1; off < 32; off <<= 1) {
        int y = __shfl_up_sync(0xFFFFFFFFu, x, off);
        if (lane >= off) x += y;
    }
    if (lane == 31) wsum[w] = x;
    __syncthreads();
    if (w == 0) {
        int y = wsum[lane];
#pragma unroll
        for (int off = 1; off < 32; off <<= 1) {
            int z = __shfl_up_sync(0xFFFFFFFFu, y, off);
            if (lane >= off) y += z;
        }
        wsum[lane] = y;
    }
    __syncthreads();
    int excl = x - s + (w > 0 ? wsum[w - 1] : 0);
    int run = excl;
#pragma unroll
    for (int i = 0; i < PER; i++) {
        int idx = base + i;
        if (idx < NN) d_rowptr[idx] = run;
        run += vals[i];
    }
    if (t == 0) d_rowptr[NN] = ET;
}

__global__ void csr_fill(const int* __restrict__ src, const int* __restrict__ dst) {
    int e = blockIdx.x * blockDim.x + threadIdx.x;
    if (e >= ET) return;
    int s, d;
    if (e < EE) { s = src[e]; d = dst[e]; }
    else        { s = d = e - EE; }
    int p = d_rowptr[d] + atomicAdd(&d_cursor[d], 1);
    d_esrc[p] = s;
    d_eid[p]  = e;
    d_edst[p] = d;
    d_pos[e]  = p;
}

// ------------------- self-loop mean edge attr ------------------------------------
__global__ void ea_mean_csr(const float* __restrict__ ea) {
    int warp = (blockIdx.x * blockDim.x + threadIdx.x) >> 5;
    int lane = threadIdx.x & 31;
    if (warp >= NN) return;
    int r0 = d_rowptr[warp], r1 = d_rowptr[warp + 1];
    float s = 0.f;
    int cnt = 0;
    for (int p = r0; p < r1; p++) {
        int e = d_eid[p];
        if (e < EE) { s += ea[(size_t)e * ED + lane]; cnt++; }
    }
    d_mean_ea[warp * ED + lane] = s / (float)(cnt > 1 ? cnt : 1);
}

// ------------------- precompute small vectors -------------------------------------
__global__ void prep(const float* __restrict__ W1, const float* __restrict__ as1,
                     const float* __restrict__ ad1,
                     const float* __restrict__ We1, const float* __restrict__ ae1,
                     const float* __restrict__ We2, const float* __restrict__ ae2) {
    int t = threadIdx.x;   // 512
    {
        int h = t >> 7, k = t & 127;
        float s = 0.f, dv = 0.f;
#pragma unroll
        for (int f = 0; f < HID; f++) {
            float w = W1[k * C1 + h * HID + f];
            s += w * as1[h * HID + f];
            dv += w * ad1[h * HID + f];
        }
        d_vs1[t] = s;
        d_vd1[t] = dv;
    }
    if (t < ED * 4) {
        int k = t >> 2, h = t & 3;
        float s = 0.f;
#pragma unroll
        for (int f = 0; f < HID; f++) s += We1[k * C1 + h * HID + f] * ae1[h * HID + f];
        d_c1[k * 4 + h] = s;
    }
    if (t < ED) {
        float s = 0.f;
#pragma unroll
        for (int f = 0; f < HID; f++) s += We2[t * HID + f] * ae2[f];
        d_c2[t] = s;
    }
}

// ------------------- node logits ----------------------------------------------------
__global__ void logits1(const float* __restrict__ x) {
    int gw = (blockIdx.x * blockDim.x + threadIdx.x) >> 5;
    int lane = threadIdx.x & 31;
    if (gw >= NN) return;
    float4 xv = ((const float4*)x)[(size_t)gw * 32 + lane];
    float r0, r1, r2, r3, q0, q1, q2, q3;
    {
        float4 v;
        v = ((const float4*)d_vs1)[0 * 32 + lane]; r0 = xv.x*v.x + xv.y*v.y + xv.z*v.z + xv.w*v.w;
        v = ((const float4*)d_vs1)[1 * 32 + lane]; r1 = xv.x*v.x + xv.y*v.y + xv.z*v.z + xv.w*v.w;
        v = ((const float4*)d_vs1)[2 * 32 + lane]; r2 = xv.x*v.x + xv.y*v.y + xv.z*v.z + xv.w*v.w;
        v = ((const float4*)d_vs1)[3 * 32 + lane]; r3 = xv.x*v.x + xv.y*v.y + xv.z*v.z + xv.w*v.w;
        v = ((const float4*)d_vd1)[0 * 32 + lane]; q0 = xv.x*v.x + xv.y*v.y + xv.z*v.z + xv.w*v.w;
        v = ((const float4*)d_vd1)[1 * 32 + lane]; q1 = xv.x*v.x + xv.y*v.y + xv.z*v.z + xv.w*v.w;
        v = ((const float4*)d_vd1)[2 * 32 + lane]; q2 = xv.x*v.x + xv.y*v.y + xv.z*v.z + xv.w*v.w;
        v = ((const float4*)d_vd1)[3 * 32 + lane]; q3 = xv.x*v.x + xv.y*v.y + xv.z*v.z + xv.w*v.w;
    }
#pragma unroll
    for (int off = 16; off >= 1; off >>= 1) {
        r0 += __shfl_xor_sync(0xFFFFFFFFu, r0, off);
        r1 += __shfl_xor_sync(0xFFFFFFFFu, r1, off);
        r2 += __shfl_xor_sync(0xFFFFFFFFu, r2, off);
        r3 += __shfl_xor_sync(0xFFFFFFFFu, r3, off);
        q0 += __shfl_xor_sync(0xFFFFFFFFu, q0, off);
        q1 += __shfl_xor_sync(0xFFFFFFFFu, q1, off);
        q2 += __shfl_xor_sync(0xFFFFFFFFu, q2, off);
        q3 += __shfl_xor_sync(0xFFFFFFFFu, q3, off);
    }
    if (lane == 0) {
        d_als1[gw * 4 + 0] = r0; d_als1[gw * 4 + 1] = r1;
        d_als1[gw * 4 + 2] = r2; d_als1[gw * 4 + 3] = r3;
        d_ald1[gw * 4 + 0] = q0; d_ald1[gw * 4 + 1] = q1;
        d_ald1[gw * 4 + 2] = q2; d_ald1[gw * 4 + 3] = q3;
    }
}

__global__ void logits2(const float* __restrict__ as2, const float* __restrict__ ad2) {
    int gw = (blockIdx.x * blockDim.x + threadIdx.x) >> 5;
    int lane = threadIdx.x & 31;
    if (gw >= NN) return;
    float2 xv = ((const float2*)d_xs2)[(size_t)gw * 32 + lane];
    float rs = xv.x * as2[lane * 2] + xv.y * as2[lane * 2 + 1];
    float rd = xv.x * ad2[lane * 2] + xv.y * ad2[lane * 2 + 1];
#pragma unroll
    for (int off = 16; off >= 1; off >>= 1) {
        rs += __shfl_xor_sync(0xFFFFFFFFu, rs, off);
        rd += __shfl_xor_sync(0xFFFFFFFFu, rd, off);
    }
    if (lane == 0) { d_als2[gw] = rs; d_ald2[gw] = rd; }
}

// ------------------- edge alphas -----------------------------------------------------
__global__ void edge_alpha1(const float* __restrict__ ea, const int* __restrict__ src,
                            const int* __restrict__ dst) {
    int e = blockIdx.x * blockDim.x + threadIdx.x;
    if (e >= ET) return;
    int s, d;
    const float* row;
    if (e < EE) { s = src[e]; d = dst[e]; row = ea + (size_t)e * ED; }
    else        { s = d = e - EE; row = d_mean_ea + (size_t)(e - EE) * ED; }
    float ec0 = 0.f, ec1 = 0.f, ec2 = 0.f, ec3 = 0.f, e2 = 0.f;
#pragma unroll
    for (int k = 0; k < ED; k++) {
        float v = __ldg(row + k);
        ec0 += v * d_c1[k * 4 + 0];
        ec1 += v * d_c1[k * 4 + 1];
        ec2 += v * d_c1[k * 4 + 2];
        ec3 += v * d_c1[k * 4 + 3];
        e2  += v * d_c2[k];
    }
    float ec[4] = {ec0, ec1, ec2, ec3};
    int p = d_pos[e];
    d_ec2[p] = e2;
    size_t pb = (size_t)p * 4;
#pragma unroll
    for (int h = 0; h < 4; h++) {
        float a = d_als1[s * 4 + h] + d_ald1[d * 4 + h] + ec[h];
        a = a > 0.f ? a : NEG * a;
        d_alpha1[pb + h] = a;
        atomicMax(&d_m1[d * 4 + h], fenc(a));
    }
}

__global__ void edge_alpha2() {
    int p = blockIdx.x * blockDim.x + threadIdx.x;
    if (p >= ET) return;
    int s = d_esrc[p], d = d_edst[p];
    float a = d_als2[s] + d_ald2[d] + d_ec2[p];
    a = a > 0.f ? a : NEG * a;
    d_alpha2[p] = a;
    atomicMax(&d_m2[d], fenc(a));
}

// ------------------- gathers (softmax fused, no atomics) ------------------------------
__global__ void __launch_bounds__(128) gather1x(const float* __restrict__ x) {
    int d = blockIdx.x, t = threadIdx.x;  // 128 threads = k index
    __shared__ __align__(16) float sh_ex[128];
    __shared__ int   sh_src[32];
    __shared__ float sh_m[4];
    __shared__ float sh_sinv[4];
    if (t < 4) sh_m[t] = fdec(d_m1[d * 4 + t]);
    int r0 = d_rowptr[d], r1 = d_rowptr[d + 1];
    float a0 = 0.f, a1 = 0.f, a2 = 0.f, a3 = 0.f, lsum = 0.f;
    __syncthreads();
    for (int p0 = r0; p0 < r1; p0 += 32) {
        int m = min(32, r1 - p0);
        if (t < m * 4) sh_ex[t] = expf(d_alpha1[(size_t)p0 * 4 + t] - sh_m[t & 3]);
        if (t < m)     sh_src[t] = d_esrc[p0 + t];
        __syncthreads();
        for (int j = 0; j < m; j++) {
            float xv = x[(size_t)sh_src[j] * FIN + t];
            float4 w = *(const float4*)&sh_ex[j * 4];
            a0 += w.x * xv; a1 += w.y * xv; a2 += w.z * xv; a3 += w.w * xv;
        }
        if (t < 4) {
            for (int j = 0; j < m; j++) lsum += sh_ex[j * 4 + t];
        }
        __syncthreads();
    }
    if (t < 4) sh_sinv[t] = 1.0f / lsum;
    __syncthreads();
    size_t base = (size_t)d * 512;
    d_tmp[base + 0 * 128 + t] = a0 * sh_sinv[0];
    d_tmp[base + 1 * 128 + t] = a1 * sh_sinv[1];
    d_tmp[base + 2 * 128 + t] = a2 * sh_sinv[2];
    d_tmp[base + 3 * 128 + t] = a3 * sh_sinv[3];
}

__global__ void __launch_bounds__(64) gather2(const float* __restrict__ bias) {
    int d = blockIdx.x, t = threadIdx.x;  // 64
    __shared__ float sh_ex[64];
    __shared__ int   sh_src[64];
    __shared__ float red[64];
    float mval = fdec(d_m2[d]);
    int r0 = d_rowptr[d], r1 = d_rowptr[d + 1];
    float acc = 0.f, tsum = 0.f;
    for (int p0 = r0; p0 < r1; p0 += 64) {
        int m = min(64, r1 - p0);
        __syncthreads();
        if (t < m) {
            float ex = expf(d_alpha2[p0 + t] - mval);
            sh_ex[t] = ex;
            sh_src[t] = d_esrc[p0 + t];
            tsum += ex;
        }
        __syncthreads();
        for (int j = 0; j < m; j++)
            acc += sh_ex[j] * d_xs2[(size_t)sh_src[j] * HID + t];
    }
    red[t] = tsum;
    __syncthreads();
    if (t == 0) {
        float s = 0.f;
        for (int j = 0; j < 64; j++) s += red[j];
        red[0] = s;
    }
    __syncthreads();
    d_out2[(size_t)d * HID + t] = acc / red[0] + bias[t];
}

// ------------------- f32x2 GEMM (parameterized) ----------------------------------------
// C[M, 64 per x-block] = A[M, K] x B[K, :], BM=128, BK=16, 256 threads.
__global__ void __launch_bounds__(256) gemm_f32x2(
    const float* __restrict__ A, int lda, int a_xstride,
    const float* __restrict__ B, int ldb,
    float* __restrict__ C, int ldc,
    const float* __restrict__ bias,
    int M, int K) {
    const int BM = 128, BK = 16;
    __shared__ __align__(16) float As[BK][BM + 4];
    __shared__ __align__(16) float Bs[BK][64];
    int tid = threadIdx.x;
    int tx = tid & 15, ty = tid >> 4;
    int m0 = blockIdx.y * BM;
    const float* Ab = A + (size_t)blockIdx.x * a_xstride;
    int bcol = blockIdx.x * 64;

    ull acc[4][4];
#pragma unroll
    for (int i = 0; i < 4; i++)
#pragma unroll
        for (int j = 0; j < 4; j++) acc[i][j] = 0ull;

    int ar = tid >> 1;
    int akb = (tid & 1) * 8;
    int gr_a = m0 + ar;
    int br = tid >> 4;
    int bc = (tid & 15) * 4;

    for (int k0 = 0; k0 < K; k0 += BK) {
        float4 a4a, a4b;
        if (gr_a < M) {
            a4a = *(const float4*)&Ab[(size_t)gr_a * lda + k0 + akb];
            a4b = *(const float4*)&Ab[(size_t)gr_a * lda + k0 + akb + 4];
        } else {
            a4a = make_float4(0.f, 0.f, 0.f, 0.f);
            a4b = a4a;
        }
        As[akb + 0][ar] = a4a.x; As[akb + 1][ar] = a4a.y;
        As[akb + 2][ar] = a4a.z; As[akb + 3][ar] = a4a.w;
        As[akb + 4][ar] = a4b.x; As[akb + 5][ar] = a4b.y;
        As[akb + 6][ar] = a4b.z; As[akb + 7][ar] = a4b.w;
        *(float4*)&Bs[br][bc] = *(const float4*)&B[(size_t)(k0 + br) * ldb + bcol + bc];
        __syncthreads();
#pragma unroll
        for (int kk = 0; kk < BK; kk++) {
            ulonglong2 ap01 = *(const ulonglong2*)&As[kk][ty * 8];
            ulonglong2 ap23 = *(const ulonglong2*)&As[kk][ty * 8 + 4];
            float4 bq = *(const float4*)&Bs[kk][tx * 4];
            ull bb0 = pack2(bq.x, bq.x);
            ull bb1 = pack2(bq.y, bq.y);
            ull bb2 = pack2(bq.z, bq.z);
            ull bb3 = pack2(bq.w, bq.w);
            ull ap[4] = {ap01.x, ap01.y, ap23.x, ap23.y};
#pragma unroll
            for (int i = 0; i < 4; i++) {
                fma2(acc[i][0], ap[i], bb0);
                fma2(acc[i][1], ap[i], bb1);
                fma2(acc[i][2], ap[i], bb2);
                fma2(acc[i][3], ap[i], bb3);
            }
        }
        __syncthreads();
    }
    float4 bv = make_float4(0.f, 0.f, 0.f, 0.f);
    if (bias) bv = *(const float4*)&bias[bcol + tx * 4];
#pragma unroll
    for (int i = 0; i < 4; i++) {
        float lo0, hi0, lo1, hi1, lo2, hi2, lo3, hi3;
        unpack2(acc[i][0], lo0, hi0);
        unpack2(acc[i][1], lo1, hi1);
        unpack2(acc[i][2], lo2, hi2);
        unpack2(acc[i][3], lo3, hi3);
        int r0 = m0 + ty * 8 + 2 * i;
        if (r0 < M)
            *(float4*)&C[(size_t)r0 * ldc + bcol + tx * 4] =
                make_float4(lo0 + bv.x, lo1 + bv.y, lo2 + bv.z, lo3 + bv.w);
        if (r0 + 1 < M)
            *(float4*)&C[(size_t)(r0 + 1) * ldc + bcol + tx * 4] =
                make_float4(hi0 + bv.x, hi1 + bv.y, hi2 + bv.z, hi3 + bv.w);
    }
}

// ------------------- batchnorm -----------------------------------------------------------
__global__ void bn_stats(const float* __restrict__ X, float* sum, float* sq, int C) {
    int t = threadIdx.x;
    int rows_per = (NN + gridDim.x - 1) / gridDim.x;
    int r0 = blockIdx.x * rows_per;
    int r1 = r0 + rows_per; if (r1 > NN) r1 = NN;
    float s = 0.f, q = 0.f;
    for (int r = r0; r < r1; r++) {
        float v = X[(size_t)r * C + t];
        s += v;
        q += v * v;
    }
    atomicAdd(&sum[t], s);
    atomicAdd(&sq[t], q);
}
__global__ void bn_apply_relu(float* X, const float* __restrict__ sum,
                              const float* __restrict__ sq,
                              const float* __restrict__ g,
                              const float* __restrict__ b, int C, int total) {
    int idx = blockIdx.x * blockDim.x + threadIdx.x;
    if (idx >= total) return;
    int t = idx % C;
    float mu = sum[t] / (float)NN;
    float var = sq[t] / (float)NN - mu * mu;
    float y = (X[idx] - mu) * rsqrtf(var + EPS) * g[t] + b[t];
    X[idx] = y > 0.f ? y : 0.f;
}

// ------------------- gating + pool ---------------------------------------------------------
__global__ void gate_kernel(const float* __restrict__ Wg, const float* __restrict__ bg) {
    int gw = (blockIdx.x * blockDim.x + threadIdx.x) >> 5;
    int lane = threadIdx.x & 31;
    if (gw >= NN) return;
    float2 xv = ((const float2*)d_out2)[(size_t)gw * 32 + lane];
    float g = xv.x * Wg[lane * 2] + xv.y * Wg[lane * 2 + 1];
#pragma unroll
    for (int off = 16; off >= 1; off >>= 1)
        g += __shfl_xor_sync(0xFFFFFFFFu, g, off);
    if (lane == 0) d_gate[gw] = g + bg[0];
}

__device__ __forceinline__ int lbound(const int* a, int n, int v) {
    int lo = 0, hi = n;
    while (lo < hi) {
        int mid = (lo + hi) >> 1;
        if (a[mid] < v) lo = mid + 1; else hi = mid;
    }
    return lo;
}

__global__ void __launch_bounds__(64) pool_kernel(const int* __restrict__ batch,
                                                  float* __restrict__ out) {
    int b = blockIdx.x, t = threadIdx.x;  // 64 threads
    __shared__ int slo, shi;
    __shared__ float red[64];
    __shared__ float sh_w[64];
    if (t == 0) { slo = lbound(batch, NN, b); shi = lbound(batch, NN, b + 1); }
    __syncthreads();
    int lo = slo, hi = shi;
    if (hi <= lo) { out[b * 64 + t] = 0.f; return; }
    // max
    float mx = -3.4e38f;
    for (int n = lo + t; n < hi; n += 64) mx = fmaxf(mx, d_gate[n]);
    red[t] = mx;
    __syncthreads();
    if (t == 0) {
        float m = red[0];
        for (int j = 1; j < 64; j++) m = fmaxf(m, red[j]);
        red[0] = m;
    }
    __syncthreads();
    float m = red[0];
    __syncthreads();
    // sum exp
    float ts = 0.f;
    for (int n = lo + t; n < hi; n += 64) ts += expf(d_gate[n] - m);
    red[t] = ts;
    __syncthreads();
    if (t == 0) {
        float s = 0.f;
        for (int j = 0; j < 64; j++) s += red[j];
        red[0] = s;
    }
    __syncthreads();
    float sinv = 1.0f / red[0];
    // weighted accumulate
    float acc = 0.f;
    for (int base = lo; base < hi; base += 64) {
        int mcnt = min(64, hi - base);
        __syncthreads();
        if (t < mcnt) sh_w[t] = expf(d_gate[base + t] - m);
        __syncthreads();
        for (int j = 0; j < mcnt; j++)
            acc += sh_w[j] * d_out2[(size_t)(base + j) * 64 + t];
    }
    out[b * 64 + t] = acc * sinv;
}

// ------------------- launch -------------------------------------------------------------------
static inline int gdiv(long long a, int b) { return (int)((a + b - 1) / b); }

extern "C" void kernel_launch(void* const* d_in, const int* in_sizes, int n_in,
                              void* d_out, int out_size) {
    const float* x     = (const float*)d_in[0];
    const float* ea    = (const float*)d_in[1];
    const int*   ei    = (const int*)d_in[2];
    const int*   batch = (const int*)d_in[3];
    const float* W1    = (const float*)d_in[4];
    const float* We1   = (const float*)d_in[5];
    const float* as1   = (const float*)d_in[6];
    const float* ad1   = (const float*)d_in[7];
    const float* ae1   = (const float*)d_in[8];
    const float* b1    = (const float*)d_in[9];
    const float* g1    = (const float*)d_in[10];
    const float* bb1   = (const float*)d_in[11];
    const float* W2    = (const float*)d_in[12];
    const float* We2   = (const float*)d_in[13];
    const float* as2   = (const float*)d_in[14];
    const float* ad2   = (const float*)d_in[15];
    const float* ae2   = (const float*)d_in[16];
    const float* b2    = (const float*)d_in[17];
    const float* g2    = (const float*)d_in[18];
    const float* bb2   = (const float*)d_in[19];
    const float* Wg    = (const float*)d_in[20];
    const float* bg    = (const float*)d_in[21];
    float* out = (float*)d_out;

    const int* src = ei;
    const int* dst = ei + EE;

    float* p_tmp;     cudaGetSymbolAddress((void**)&p_tmp, d_tmp);
    float* p_out1;    cudaGetSymbolAddress((void**)&p_out1, d_out1);
    float* p_xs2;     cudaGetSymbolAddress((void**)&p_xs2, d_xs2);
    float* p_out2;    cudaGetSymbolAddress((void**)&p_out2, d_out2);
    float* p_colsum1; cudaGetSymbolAddress((void**)&p_colsum1, d_colsum1);
    float* p_colsq1;  cudaGetSymbolAddress((void**)&p_colsq1, d_colsq1);
    float* p_colsum2; cudaGetSymbolAddress((void**)&p_colsum2, d_colsum2);
    float* p_colsq2;  cudaGetSymbolAddress((void**)&p_colsq2, d_colsq2);

    init_all<<<gdiv(NN * 4, 256), 256>>>();
    hist_kernel<<<gdiv(EE, 256), 256>>>(dst);
    scan_kernel<<<1, 1024>>>();
    csr_fill<<<gdiv(ET, 256), 256>>>(src, dst);
    ea_mean_csr<<<gdiv(NN * 32, 256), 256>>>(ea);
    prep<<<1, 512>>>(W1, as1, ad1, We1, ae1, We2, ae2);

    // ---- layer 1 ----
    logits1<<<gdiv((long long)NN * 32, 256), 256>>>(x);
    edge_alpha1<<<gdiv(ET, 256), 256>>>(ea, src, dst);
    gather1x<<<NN, 128>>>(x);
    {
        dim3 g(4, gdiv(NN, 128));
        gemm_f32x2<<<g, 256>>>(p_tmp, 512, 128, W1, C1, p_out1, C1, b1, NN, FIN);
    }
    bn_stats<<<128, C1>>>(p_out1, p_colsum1, p_colsq1, C1);
    bn_apply_relu<<<gdiv(NN * C1, 256), 256>>>(p_out1, p_colsum1, p_colsq1, g1, bb1, C1, NN * C1);

    // ---- layer 2 ----
    {
        dim3 g(1, gdiv(NN, 128));
        gemm_f32x2<<<g, 256>>>(p_out1, C1, 0, W2, HID, p_xs2, HID, (const float*)0, NN, C1);
    }
    logits2<<<gdiv((long long)NN * 32, 256), 256>>>(as2, ad2);
    edge_alpha2<<<gdiv(ET, 256), 256>>>();
    gather2<<<NN, 64>>>(b2);
    bn_stats<<<128, HID>>>(p_out2, p_colsum2, p_colsq2, HID);
    bn_apply_relu<<<gdiv(NN * HID, 256), 256>>>(p_out2, p_colsum2, p_colsq2, g2, bb2, HID, NN * HID);

    // ---- pooling ----
    gate_kernel<<<gdiv((long long)NN * 32, 256), 256>>>(Wg, bg);
    pool_kernel<<<BB, 64>>>(batch, out);
}

// round 7
// speedup vs baseline: 4.6118x; 1.1675x over previous
#include <cuda_runtime.h>
#include <math_constants.h>

#define NN 30000
#define EE 480000
#define ET (EE + NN)
#define BB 64
#define FIN 128
#define HID 64
#define ED 32
#define C1 256
#define NEG 0.2f
#define EPS 1e-5f

typedef unsigned long long ull;

// ------------------- scratch -------------------------------------------------
__device__ int      d_deg[NN];
__device__ int      d_rowptr[NN + 1];
__device__ int      d_cursor[NN];
__device__ int      d_esrc[ET];
__device__ int      d_edst[ET];
__device__ int      d_pos[EE];
__device__ int      d_selfpos[NN];

__device__ float    d_vs1[512];
__device__ float    d_vd1[512];
__device__ float    d_c1[ED * 4];
__device__ float    d_c2[ED];
__device__ float    d_als1[NN * 4];
__device__ float    d_ald1[NN * 4];
__device__ float    d_ecs[(size_t)ET * 4];      // CSR order, raw ea.c1 per head
__device__ float    d_ec2[ET];                  // CSR order, ea.c2
__device__ float    d_alpha1[(size_t)ET * 4];   // CSR order, lrelu logits
__device__ float    d_tmp[(size_t)NN * 512];    // [n][h*128+k]
__device__ float    d_out1[(size_t)NN * C1];
__device__ float    d_colsum1[C1];
__device__ float    d_colsq1[C1];
__device__ float    d_xs2[(size_t)NN * HID];
__device__ float    d_als2[NN];
__device__ float    d_ald2[NN];
__device__ float    d_alpha2[ET];
__device__ float    d_out2[(size_t)NN * HID];
__device__ float    d_colsum2[HID];
__device__ float    d_colsq2[HID];
__device__ float    d_gate[NN];

// ------------------- helpers -------------------------------------------------
__device__ __forceinline__ ull pack2(float lo, float hi) {
    ull r;
    asm("mov.b64 %0, {%1, %2};" : "=l"(r) : "f"(lo), "f"(hi));
    return r;
}
__device__ __forceinline__ void unpack2(ull v, float& lo, float& hi) {
    asm("mov.b64 {%0, %1}, %2;" : "=f"(lo), "=f"(hi) : "l"(v));
}
__device__ __forceinline__ void fma2(ull& acc, ull a, ull b) {
    asm("fma.rn.f32x2 %0, %1, %2, %0;" : "+l"(acc) : "l"(a), "l"(b));
}
__device__ __forceinline__ float lrelu(float a) { return a > 0.f ? a : NEG * a; }

// ------------------- init ------------------------------------------------------
__global__ void init_all() {
    int i = blockIdx.x * blockDim.x + threadIdx.x;
    if (i < NN) { d_deg[i] = 1; d_cursor[i] = 0; }
    if (i < C1) { d_colsum1[i] = 0.f; d_colsq1[i] = 0.f; }
    if (i < HID) { d_colsum2[i] = 0.f; d_colsq2[i] = 0.f; }
}

// ------------------- CSR build --------------------------------------------------
__global__ void hist_kernel(const int* __restrict__ dst) {
    int e = blockIdx.x * blockDim.x + threadIdx.x;
    if (e < EE) atomicAdd(&d_deg[dst[e]], 1);
}

__global__ void scan_kernel() {
    __shared__ int wsum[32];
    const int PER = 30;
    int t = threadIdx.x;
    int base = t * PER;
    int vals[PER];
    int s = 0;
#pragma unroll
    for (int i = 0; i < PER; i++) {
        int idx = base + i;
        vals[i] = (idx < NN) ? d_deg[idx] : 0;
        s += vals[i];
    }
    int lane = t & 31, w = t >> 5;
    int x = s;
#pragma unroll
    for (int off = 1; off < 32; off <<= 1) {
        int y = __shfl_up_sync(0xFFFFFFFFu, x, off);
        if (lane >= off) x += y;
    }
    if (lane == 31) wsum[w] = x;
    __syncthreads();
    if (w == 0) {
        int y = wsum[lane];
#pragma unroll
        for (int off = 1; off < 32; off <<= 1) {
            int z = __shfl_up_sync(0xFFFFFFFFu, y, off);
            if (lane >= off) y += z;
        }
        wsum[lane] = y;
    }
    __syncthreads();
    int excl = x - s + (w > 0 ? wsum[w - 1] : 0);
    int run = excl;
#pragma unroll
    for (int i = 0; i < PER; i++) {
        int idx = base + i;
        if (idx < NN) d_rowptr[idx] = run;
        run += vals[i];
    }
    if (t == 0) d_rowptr[NN] = ET;
}

__global__ void csr_fill(const int* __restrict__ src, const int* __restrict__ dst) {
    int e = blockIdx.x * blockDim.x + threadIdx.x;
    if (e >= ET) return;
    int s, d;
    if (e < EE) { s = src[e]; d = dst[e]; }
    else        { s = d = e - EE; }
    int p = d_rowptr[d] + atomicAdd(&d_cursor[d], 1);
    d_esrc[p] = s;
    d_edst[p] = d;
    if (e < EE) d_pos[e] = p;
    else        d_selfpos[e - EE] = p;
}

// ------------------- precompute small vectors -------------------------------------
__global__ void prep(const float* __restrict__ W1, const float* __restrict__ as1,
                     const float* __restrict__ ad1,
                     const float* __restrict__ We1, const float* __restrict__ ae1,
                     const float* __restrict__ We2, const float* __restrict__ ae2) {
    int t = threadIdx.x;   // 512
    {
        int h = t >> 7, k = t & 127;
        float s = 0.f, dv = 0.f;
#pragma unroll
        for (int f = 0; f < HID; f++) {
            float w = W1[k * C1 + h * HID + f];
            s += w * as1[h * HID + f];
            dv += w * ad1[h * HID + f];
        }
        d_vs1[t] = s;
        d_vd1[t] = dv;
    }
    if (t < ED * 4) {
        int k = t >> 2, h = t & 3;
        float s = 0.f;
#pragma unroll
        for (int f = 0; f < HID; f++) s += We1[k * C1 + h * HID + f] * ae1[h * HID + f];
        d_c1[k * 4 + h] = s;
    }
    if (t < ED) {
        float s = 0.f;
#pragma unroll
        for (int f = 0; f < HID; f++) s += We2[t * HID + f] * ae2[f];
        d_c2[t] = s;
    }
}

// ------------------- node logits (layer 1) ---------------------------------------
__global__ void logits1(const float* __restrict__ x) {
    int gw = (blockIdx.x * blockDim.x + threadIdx.x) >> 5;
    int lane = threadIdx.x & 31;
    if (gw >= NN) return;
    float4 xv = ((const float4*)x)[(size_t)gw * 32 + lane];
    float r0, r1, r2, r3, q0, q1, q2, q3;
    {
        float4 v;
        v = ((const float4*)d_vs1)[0 * 32 + lane]; r0 = xv.x*v.x + xv.y*v.y + xv.z*v.z + xv.w*v.w;
        v = ((const float4*)d_vs1)[1 * 32 + lane]; r1 = xv.x*v.x + xv.y*v.y + xv.z*v.z + xv.w*v.w;
        v = ((const float4*)d_vs1)[2 * 32 + lane]; r2 = xv.x*v.x + xv.y*v.y + xv.z*v.z + xv.w*v.w;
        v = ((const float4*)d_vs1)[3 * 32 + lane]; r3 = xv.x*v.x + xv.y*v.y + xv.z*v.z + xv.w*v.w;
        v = ((const float4*)d_vd1)[0 * 32 + lane]; q0 = xv.x*v.x + xv.y*v.y + xv.z*v.z + xv.w*v.w;
        v = ((const float4*)d_vd1)[1 * 32 + lane]; q1 = xv.x*v.x + xv.y*v.y + xv.z*v.z + xv.w*v.w;
        v = ((const float4*)d_vd1)[2 * 32 + lane]; q2 = xv.x*v.x + xv.y*v.y + xv.z*v.z + xv.w*v.w;
        v = ((const float4*)d_vd1)[3 * 32 + lane]; q3 = xv.x*v.x + xv.y*v.y + xv.z*v.z + xv.w*v.w;
    }
#pragma unroll
    for (int off = 16; off >= 1; off >>= 1) {
        r0 += __shfl_xor_sync(0xFFFFFFFFu, r0, off);
        r1 += __shfl_xor_sync(0xFFFFFFFFu, r1, off);
        r2 += __shfl_xor_sync(0xFFFFFFFFu, r2, off);
        r3 += __shfl_xor_sync(0xFFFFFFFFu, r3, off);
        q0 += __shfl_xor_sync(0xFFFFFFFFu, q0, off);
        q1 += __shfl_xor_sync(0xFFFFFFFFu, q1, off);
        q2 += __shfl_xor_sync(0xFFFFFFFFu, q2, off);
        q3 += __shfl_xor_sync(0xFFFFFFFFu, q3, off);
    }
    if (lane == 0) {
        d_als1[gw * 4 + 0] = r0; d_als1[gw * 4 + 1] = r1;
        d_als1[gw * 4 + 2] = r2; d_als1[gw * 4 + 3] = r3;
        d_ald1[gw * 4 + 0] = q0; d_ald1[gw * 4 + 1] = q1;
        d_ald1[gw * 4 + 2] = q2; d_ald1[gw * 4 + 3] = q3;
    }
}

// ------------------- edge alphas (real edges; no atomics) --------------------------
__global__ void edge_alpha1(const float* __restrict__ ea, const int* __restrict__ src,
                            const int* __restrict__ dst) {
    int e = blockIdx.x * blockDim.x + threadIdx.x;
    if (e >= EE) return;
    int s = src[e], d = dst[e];
    const float4* row = (const float4*)(ea + (size_t)e * ED);
    float ec0 = 0.f, ec1 = 0.f, ec2 = 0.f, ec3 = 0.f, e2 = 0.f;
#pragma unroll
    for (int q = 0; q < 8; q++) {
        float4 v = __ldg(row + q);
        int k = q * 4;
        ec0 += v.x * d_c1[(k+0)*4+0] + v.y * d_c1[(k+1)*4+0] + v.z * d_c1[(k+2)*4+0] + v.w * d_c1[(k+3)*4+0];
        ec1 += v.x * d_c1[(k+0)*4+1] + v.y * d_c1[(k+1)*4+1] + v.z * d_c1[(k+2)*4+1] + v.w * d_c1[(k+3)*4+1];
        ec2 += v.x * d_c1[(k+0)*4+2] + v.y * d_c1[(k+1)*4+2] + v.z * d_c1[(k+2)*4+2] + v.w * d_c1[(k+3)*4+2];
        ec3 += v.x * d_c1[(k+0)*4+3] + v.y * d_c1[(k+1)*4+3] + v.z * d_c1[(k+2)*4+3] + v.w * d_c1[(k+3)*4+3];
        e2  += v.x * d_c2[k+0] + v.y * d_c2[k+1] + v.z * d_c2[k+2] + v.w * d_c2[k+3];
    }
    int p = d_pos[e];
    *(float4*)&d_ecs[(size_t)p * 4] = make_float4(ec0, ec1, ec2, ec3);
    d_ec2[p] = e2;
    float4 a;
    a.x = lrelu(d_als1[s * 4 + 0] + d_ald1[d * 4 + 0] + ec0);
    a.y = lrelu(d_als1[s * 4 + 1] + d_ald1[d * 4 + 1] + ec1);
    a.z = lrelu(d_als1[s * 4 + 2] + d_ald1[d * 4 + 2] + ec2);
    a.w = lrelu(d_als1[s * 4 + 3] + d_ald1[d * 4 + 3] + ec3);
    *(float4*)&d_alpha1[(size_t)p * 4] = a;
}

// self-loop logits from row means (linearity of ea.c)
__global__ void selfloop1() {
    int i = (blockIdx.x * blockDim.x + threadIdx.x) >> 5;
    int lane = threadIdx.x & 31;
    if (i >= NN) return;
    int r0 = d_rowptr[i], r1 = d_rowptr[i + 1];
    int L = r1 - r0;
    int ps = d_selfpos[i];
    float s0 = 0.f, s1 = 0.f, s2 = 0.f, s3 = 0.f, s4 = 0.f;
    for (int idx = lane; idx < L; idx += 32) {
        int p = r0 + idx;
        if (p == ps) continue;
        float4 v = *(const float4*)&d_ecs[(size_t)p * 4];
        s0 += v.x; s1 += v.y; s2 += v.z; s3 += v.w;
        s4 += d_ec2[p];
    }
#pragma unroll
    for (int off = 16; off >= 1; off >>= 1) {
        s0 += __shfl_xor_sync(0xFFFFFFFFu, s0, off);
        s1 += __shfl_xor_sync(0xFFFFFFFFu, s1, off);
        s2 += __shfl_xor_sync(0xFFFFFFFFu, s2, off);
        s3 += __shfl_xor_sync(0xFFFFFFFFu, s3, off);
        s4 += __shfl_xor_sync(0xFFFFFFFFu, s4, off);
    }
    if (lane == 0) {
        float cnt = (float)(L - 1 > 1 ? L - 1 : 1);
        float m0 = s0 / cnt, m1 = s1 / cnt, m2 = s2 / cnt, m3 = s3 / cnt;
        float4 a;
        a.x = lrelu(d_als1[i * 4 + 0] + d_ald1[i * 4 + 0] + m0);
        a.y = lrelu(d_als1[i * 4 + 1] + d_ald1[i * 4 + 1] + m1);
        a.z = lrelu(d_als1[i * 4 + 2] + d_ald1[i * 4 + 2] + m2);
        a.w = lrelu(d_als1[i * 4 + 3] + d_ald1[i * 4 + 3] + m3);
        *(float4*)&d_alpha1[(size_t)ps * 4] = a;
        d_ec2[ps] = s4 / cnt;
    }
}

// ------------------- gather layer1 (4 warps, float4 rows, inline max) ---------------
__global__ void __launch_bounds__(128) gather1x(const float* __restrict__ x) {
    int d = blockIdx.x, t = threadIdx.x;
    int w = t >> 5, lane = t & 31;
    int r0 = d_rowptr[d], r1 = d_rowptr[d + 1];
    int L = r1 - r0;
    __shared__ float shred[128];
    __shared__ __align__(16) float sh_ex[128];
    __shared__ int sh_src[32];
    __shared__ float shacc[4 * 512];
    __shared__ float sh_sinv[4];

    // phase 1: per-head max (head = index & 3)
    float mx = -CUDART_INF_F;
    for (int v = t; v < 4 * L; v += 128) mx = fmaxf(mx, d_alpha1[(size_t)4 * r0 + v]);
    shred[t] = mx;
    __syncthreads();
#pragma unroll
    for (int off = 64; off >= 4; off >>= 1) {
        if (t < off) shred[t] = fmaxf(shred[t], shred[t + off]);
        __syncthreads();
    }
    float mymax = shred[t & 3];
    __syncthreads();

    // phase 2: exp + weighted accumulate
    float a00=0,a01=0,a02=0,a03=0, a10=0,a11=0,a12=0,a13=0;
    float a20=0,a21=0,a22=0,a23=0, a30=0,a31=0,a32=0,a33=0;
    float lsum = 0.f;
    const float4* x4 = (const float4*)x;
    for (int p0 = r0; p0 < r1; p0 += 32) {
        int m = min(32, r1 - p0);
        __syncthreads();
        if (t < 4 * m) {
            float e = expf(d_alpha1[(size_t)4 * p0 + t] - mymax);
            sh_ex[t] = e;
            lsum += e;
        }
        if (t < m) sh_src[t] = d_esrc[p0 + t];
        __syncthreads();
        for (int j = w; j < m; j += 4) {
            float4 xv = x4[(size_t)sh_src[j] * 32 + lane];
            float4 ex = *(const float4*)&sh_ex[4 * j];
            a00 += ex.x * xv.x; a01 += ex.x * xv.y; a02 += ex.x * xv.z; a03 += ex.x * xv.w;
            a10 += ex.y * xv.x; a11 += ex.y * xv.y; a12 += ex.y * xv.z; a13 += ex.y * xv.w;
            a20 += ex.z * xv.x; a21 += ex.z * xv.y; a22 += ex.z * xv.z; a23 += ex.z * xv.w;
            a30 += ex.w * xv.x; a31 += ex.w * xv.y; a32 += ex.w * xv.z; a33 += ex.w * xv.w;
        }
    }
    // sum of exp per head
    __syncthreads();
    shred[t] = lsum;
    __syncthreads();
#pragma unroll
    for (int off = 64; off >= 4; off >>= 1) {
        if (t < off) shred[t] += shred[t + off];
        __syncthreads();
    }
    if (t < 4) sh_sinv[t] = 1.0f / shred[t];
    // cross-warp reduce of accumulators
    int cb = lane * 4;
    shacc[w * 512 + 0 * 128 + cb + 0] = a00; shacc[w * 512 + 0 * 128 + cb + 1] = a01;
    shacc[w * 512 + 0 * 128 + cb + 2] = a02; shacc[w * 512 + 0 * 128 + cb + 3] = a03;
    shacc[w * 512 + 1 * 128 + cb + 0] = a10; shacc[w * 512 + 1 * 128 + cb + 1] = a11;
    shacc[w * 512 + 1 * 128 + cb + 2] = a12; shacc[w * 512 + 1 * 128 + cb + 3] = a13;
    shacc[w * 512 + 2 * 128 + cb + 0] = a20; shacc[w * 512 + 2 * 128 + cb + 1] = a21;
    shacc[w * 512 + 2 * 128 + cb + 2] = a22; shacc[w * 512 + 2 * 128 + cb + 3] = a23;
    shacc[w * 512 + 3 * 128 + cb + 0] = a30; shacc[w * 512 + 3 * 128 + cb + 1] = a31;
    shacc[w * 512 + 3 * 128 + cb + 2] = a32; shacc[w * 512 + 3 * 128 + cb + 3] = a33;
    __syncthreads();
    size_t base = (size_t)d * 512;
#pragma unroll
    for (int h = 0; h < 4; h++) {
        float v = shacc[0 * 512 + h * 128 + t] + shacc[1 * 512 + h * 128 + t]
                + shacc[2 * 512 + h * 128 + t] + shacc[3 * 512 + h * 128 + t];
        d_tmp[base + h * 128 + t] = v * sh_sinv[h];
    }
}

// ------------------- GEMM1: out1 = tmp(heads) @ W1 + b1, fused BN stats -------------
__global__ void __launch_bounds__(256) gemm1_stats(
    const float* __restrict__ A, const float* __restrict__ B,
    float* __restrict__ C, const float* __restrict__ bias) {
    const int BK = 16;
    __shared__ __align__(16) float As[BK][128 + 4];
    __shared__ __align__(16) float Bs[BK][64];
    __shared__ float reds[16][64];
    __shared__ float redq[16][64];
    int tid = threadIdx.x;
    int tx = tid & 15, ty = tid >> 4;
    int m0 = blockIdx.y * 128;
    const float* Ab = A + (size_t)blockIdx.x * 128;   // head offset in 512-wide rows
    int bcol = blockIdx.x * 64;

    ull acc[4][4];
#pragma unroll
    for (int i = 0; i < 4; i++)
#pragma unroll
        for (int j = 0; j < 4; j++) acc[i][j] = 0ull;

    int ar = tid >> 1;
    int akb = (tid & 1) * 8;
    int gr_a = m0 + ar;
    int br = tid >> 4;
    int bc = (tid & 15) * 4;

    for (int k0 = 0; k0 < FIN; k0 += BK) {
        float4 a4a, a4b;
        if (gr_a < NN) {
            a4a = *(const float4*)&Ab[(size_t)gr_a * 512 + k0 + akb];
            a4b = *(const float4*)&Ab[(size_t)gr_a * 512 + k0 + akb + 4];
        } else {
            a4a = make_float4(0.f, 0.f, 0.f, 0.f);
            a4b = a4a;
        }
        As[akb + 0][ar] = a4a.x; As[akb + 1][ar] = a4a.y;
        As[akb + 2][ar] = a4a.z; As[akb + 3][ar] = a4a.w;
        As[akb + 4][ar] = a4b.x; As[akb + 5][ar] = a4b.y;
        As[akb + 6][ar] = a4b.z; As[akb + 7][ar] = a4b.w;
        *(float4*)&Bs[br][bc] = *(const float4*)&B[(size_t)(k0 + br) * C1 + bcol + bc];
        __syncthreads();
#pragma unroll
        for (int kk = 0; kk < BK; kk++) {
            ulonglong2 ap01 = *(const ulonglong2*)&As[kk][ty * 8];
            ulonglong2 ap23 = *(const ulonglong2*)&As[kk][ty * 8 + 4];
            float4 bq = *(const float4*)&Bs[kk][tx * 4];
            ull bb0 = pack2(bq.x, bq.x);
            ull bb1 = pack2(bq.y, bq.y);
            ull bb2 = pack2(bq.z, bq.z);
            ull bb3 = pack2(bq.w, bq.w);
            ull ap[4] = {ap01.x, ap01.y, ap23.x, ap23.y};
#pragma unroll
            for (int i = 0; i < 4; i++) {
                fma2(acc[i][0], ap[i], bb0);
                fma2(acc[i][1], ap[i], bb1);
                fma2(acc[i][2], ap[i], bb2);
                fma2(acc[i][3], ap[i], bb3);
            }
        }
        __syncthreads();
    }
    float4 bv = *(const float4*)&bias[bcol + tx * 4];
    float psum[4] = {0.f, 0.f, 0.f, 0.f};
    float psq[4]  = {0.f, 0.f, 0.f, 0.f};
#pragma unroll
    for (int i = 0; i < 4; i++) {
        float lo0, hi0, lo1, hi1, lo2, hi2, lo3, hi3;
        unpack2(acc[i][0], lo0, hi0);
        unpack2(acc[i][1], lo1, hi1);
        unpack2(acc[i][2], lo2, hi2);
        unpack2(acc[i][3], lo3, hi3);
        int r0 = m0 + ty * 8 + 2 * i;
        float y0 = lo0 + bv.x, y1 = lo1 + bv.y, y2 = lo2 + bv.z, y3 = lo3 + bv.w;
        float z0 = hi0 + bv.x, z1 = hi1 + bv.y, z2 = hi2 + bv.z, z3 = hi3 + bv.w;
        if (r0 < NN) {
            *(float4*)&C[(size_t)r0 * C1 + bcol + tx * 4] = make_float4(y0, y1, y2, y3);
            psum[0] += y0; psum[1] += y1; psum[2] += y2; psum[3] += y3;
            psq[0] += y0 * y0; psq[1] += y1 * y1; psq[2] += y2 * y2; psq[3] += y3 * y3;
        }
        if (r0 + 1 < NN) {
            *(float4*)&C[(size_t)(r0 + 1) * C1 + bcol + tx * 4] = make_float4(z0, z1, z2, z3);
            psum[0] += z0; psum[1] += z1; psum[2] += z2; psum[3] += z3;
            psq[0] += z0 * z0; psq[1] += z1 * z1; psq[2] += z2 * z2; psq[3] += z3 * z3;
        }
    }
#pragma unroll
    for (int c = 0; c < 4; c++) {
        reds[ty][tx * 4 + c] = psum[c];
        redq[ty][tx * 4 + c] = psq[c];
    }
    __syncthreads();
    if (tid < 64) {
        float s = 0.f, q = 0.f;
#pragma unroll
        for (int i = 0; i < 16; i++) { s += reds[i][tid]; q += redq[i][tid]; }
        atomicAdd(&d_colsum1[bcol + tid], s);
        atomicAdd(&d_colsq1[bcol + tid], q);
    }
}

// ------------------- GEMM2: xs2 = BNReLU(out1) @ W2, fused logits2 ------------------
__global__ void __launch_bounds__(256) gemm2_fused(
    const float* __restrict__ A, const float* __restrict__ B,
    float* __restrict__ C, const float* __restrict__ g1bn,
    const float* __restrict__ b1bn, const float* __restrict__ as2,
    const float* __restrict__ ad2) {
    const int BK = 16;
    __shared__ __align__(16) float As[BK][128 + 4];
    __shared__ __align__(16) float Bs[BK][64];
    __shared__ float sc[C1];
    __shared__ float sf[C1];
    int tid = threadIdx.x;
    int tx = tid & 15, ty = tid >> 4;
    int m0 = blockIdx.y * 128;

    {   // BN scale/shift
        float mu = d_colsum1[tid] / (float)NN;
        float var = d_colsq1[tid] / (float)NN - mu * mu;
        float rs = rsqrtf(var + EPS) * g1bn[tid];
        sc[tid] = rs;
        sf[tid] = b1bn[tid] - mu * rs;
    }
    __syncthreads();

    ull acc[4][4];
#pragma unroll
    for (int i = 0; i < 4; i++)
#pragma unroll
        for (int j = 0; j < 4; j++) acc[i][j] = 0ull;

    int ar = tid >> 1;
    int akb = (tid & 1) * 8;
    int gr_a = m0 + ar;
    int br = tid >> 4;
    int bc = (tid & 15) * 4;

    for (int k0 = 0; k0 < C1; k0 += BK) {
        float4 a4a, a4b;
        if (gr_a < NN) {
            a4a = *(const float4*)&A[(size_t)gr_a * C1 + k0 + akb];
            a4b = *(const float4*)&A[(size_t)gr_a * C1 + k0 + akb + 4];
        } else {
            a4a = make_float4(0.f, 0.f, 0.f, 0.f);
            a4b = a4a;
        }
        int kb = k0 + akb;
        As[akb + 0][ar] = fmaxf(fmaf(a4a.x, sc[kb + 0], sf[kb + 0]), 0.f);
        As[akb + 1][ar] = fmaxf(fmaf(a4a.y, sc[kb + 1], sf[kb + 1]), 0.f);
        As[akb + 2][ar] = fmaxf(fmaf(a4a.z, sc[kb + 2], sf[kb + 2]), 0.f);
        As[akb + 3][ar] = fmaxf(fmaf(a4a.w, sc[kb + 3], sf[kb + 3]), 0.f);
        As[akb + 4][ar] = fmaxf(fmaf(a4b.x, sc[kb + 4], sf[kb + 4]), 0.f);
        As[akb + 5][ar] = fmaxf(fmaf(a4b.y, sc[kb + 5], sf[kb + 5]), 0.f);
        As[akb + 6][ar] = fmaxf(fmaf(a4b.z, sc[kb + 6], sf[kb + 6]), 0.f);
        As[akb + 7][ar] = fmaxf(fmaf(a4b.w, sc[kb + 7], sf[kb + 7]), 0.f);
        *(float4*)&Bs[br][bc] = *(const float4*)&B[(size_t)(k0 + br) * HID + bc];
        __syncthreads();
#pragma unroll
        for (int kk = 0; kk < BK; kk++) {
            ulonglong2 ap01 = *(const ulonglong2*)&As[kk][ty * 8];
            ulonglong2 ap23 = *(const ulonglong2*)&As[kk][ty * 8 + 4];
            float4 bq = *(const float4*)&Bs[kk][tx * 4];
            ull bb0 = pack2(bq.x, bq.x);
            ull bb1 = pack2(bq.y, bq.y);
            ull bb2 = pack2(bq.z, bq.z);
            ull bb3 = pack2(bq.w, bq.w);
            ull ap[4] = {ap01.x, ap01.y, ap23.x, ap23.y};
#pragma unroll
            for (int i = 0; i < 4; i++) {
                fma2(acc[i][0], ap[i], bb0);
                fma2(acc[i][1], ap[i], bb1);
                fma2(acc[i][2], ap[i], bb2);
                fma2(acc[i][3], ap[i], bb3);
            }
        }
        __syncthreads();
    }
    float4 av = *(const float4*)&as2[tx * 4];
    float4 dv = *(const float4*)&ad2[tx * 4];
    float ps8[8], pd8[8];
#pragma unroll
    for (int i = 0; i < 4; i++) {
        float lo0, hi0, lo1, hi1, lo2, hi2, lo3, hi3;
        unpack2(acc[i][0], lo0, hi0);
        unpack2(acc[i][1], lo1, hi1);
        unpack2(acc[i][2], lo2, hi2);
        unpack2(acc[i][3], lo3, hi3);
        int r0 = m0 + ty * 8 + 2 * i;
        if (r0 < NN)
            *(float4*)&C[(size_t)r0 * HID + tx * 4] = make_float4(lo0, lo1, lo2, lo3);
        if (r0 + 1 < NN)
            *(float4*)&C[(size_t)(r0 + 1) * HID + tx * 4] = make_float4(hi0, hi1, hi2, hi3);
        ps8[2 * i]     = lo0 * av.x + lo1 * av.y + lo2 * av.z + lo3 * av.w;
        ps8[2 * i + 1] = hi0 * av.x + hi1 * av.y + hi2 * av.z + hi3 * av.w;
        pd8[2 * i]     = lo0 * dv.x + lo1 * dv.y + lo2 * dv.z + lo3 * dv.w;
        pd8[2 * i + 1] = hi0 * dv.x + hi1 * dv.y + hi2 * dv.z + hi3 * dv.w;
    }
    float* red = &As[0][0];   // 128 rows x 16
    __syncthreads();
#pragma unroll
    for (int i = 0; i < 8; i++) red[(ty * 8 + i) * 16 + tx] = ps8[i];
    __syncthreads();
    if (tid < 128 && m0 + tid < NN) {
        float s = 0.f;
#pragma unroll
        for (int j = 0; j < 16; j++) s += red[tid * 16 + j];
        d_als2[m0 + tid] = s;
    }
    __syncthreads();
#pragma unroll
    for (int i = 0; i < 8; i++) red[(ty * 8 + i) * 16 + tx] = pd8[i];
    __syncthreads();
    if (tid < 128 && m0 + tid < NN) {
        float s = 0.f;
#pragma unroll
        for (int j = 0; j < 16; j++) s += red[tid * 16 + j];
        d_ald2[m0 + tid] = s;
    }
}

// ------------------- layer-2 edge alphas (CSR order, no atomics) ---------------------
__global__ void edge_alpha2() {
    int p = blockIdx.x * blockDim.x + threadIdx.x;
    if (p >= ET) return;
    int s = d_esrc[p], d = d_edst[p];
    d_alpha2[p] = lrelu(d_als2[s] + d_ald2[d] + d_ec2[p]);
}

// ------------------- gather layer2 (4 warps, float2 rows, inline max) ----------------
__global__ void __launch_bounds__(128) gather2(const float* __restrict__ bias) {
    int d = blockIdx.x, t = threadIdx.x;
    int w = t >> 5, lane = t & 31;
    int r0 = d_rowptr[d], r1 = d_rowptr[d + 1];
    int L = r1 - r0;
    __shared__ float shred[128];
    __shared__ float sh_ex[64];
    __shared__ int sh_src[64];
    __shared__ float shacc[4 * 64];
    __shared__ float sh_tot;

    float mx = -CUDART_INF_F;
    for (int v = t; v < L; v += 128) mx = fmaxf(mx, d_alpha2[r0 + v]);
    shred[t] = mx;
    __syncthreads();
#pragma unroll
    for (int off = 64; off >= 1; off >>= 1) {
        if (t < off) shred[t] = fmaxf(shred[t], shred[t + off]);
        __syncthreads();
    }
    float mymax = shred[0];
    __syncthreads();

    float ax = 0.f, ay = 0.f, lsum = 0.f;
    const float2* x2 = (const float2*)d_xs2;
    for (int p0 = r0; p0 < r1; p0 += 64) {
        int m = min(64, r1 - p0);
        __syncthreads();
        if (t < m) {
            float e = expf(d_alpha2[p0 + t] - mymax);
            sh_ex[t] = e;
            lsum += e;
            sh_src[t] = d_esrc[p0 + t];
        }
        __syncthreads();
        for (int j = w; j < m; j += 4) {
            float2 xv = x2[(size_t)sh_src[j] * 32 + lane];
            float e = sh_ex[j];
            ax += e * xv.x;
            ay += e * xv.y;
        }
    }
    __syncthreads();
    shred[t] = lsum;
    __syncthreads();
#pragma unroll
    for (int off = 64; off >= 1; off >>= 1) {
        if (t < off) shred[t] += shred[t + off];
        __syncthreads();
    }
    if (t == 0) sh_tot = 1.0f / shred[0];
    shacc[w * 64 + lane * 2]     = ax;
    shacc[w * 64 + lane * 2 + 1] = ay;
    __syncthreads();
    if (t < 64) {
        float v = shacc[0 * 64 + t] + shacc[1 * 64 + t] + shacc[2 * 64 + t] + shacc[3 * 64 + t];
        d_out2[(size_t)d * HID + t] = v * sh_tot + bias[t];
    }
}

// ------------------- bn2 stats -------------------------------------------------------
__global__ void bn_stats2() {
    int t = threadIdx.x;  // 64
    int rows_per = (NN + gridDim.x - 1) / gridDim.x;
    int r0 = blockIdx.x * rows_per;
    int r1 = r0 + rows_per; if (r1 > NN) r1 = NN;
    float s = 0.f, q = 0.f;
    for (int r = r0; r < r1; r++) {
        float v = d_out2[(size_t)r * HID + t];
        s += v;
        q += v * v;
    }
    atomicAdd(&d_colsum2[t], s);
    atomicAdd(&d_colsq2[t], q);
}

// ------------------- gate (applies BN2+ReLU in place) ---------------------------------
__global__ void gate_bn(const float* __restrict__ g2, const float* __restrict__ b2,
                        const float* __restrict__ Wg, const float* __restrict__ bg) {
    int n = (blockIdx.x * blockDim.x + threadIdx.x) >> 5;
    int lane = threadIdx.x & 31;
    if (n >= NN) return;
    int c0 = lane * 2, c1 = c0 + 1;
    float2 v = ((const float2*)d_out2)[(size_t)n * 32 + lane];
    float mu0 = d_colsum2[c0] / (float)NN;
    float var0 = d_colsq2[c0] / (float)NN - mu0 * mu0;
    float y0 = fmaxf((v.x - mu0) * rsqrtf(var0 + EPS) * __ldg(g2 + c0) + __ldg(b2 + c0), 0.f);
    float mu1 = d_colsum2[c1] / (float)NN;
    float var1 = d_colsq2[c1] / (float)NN - mu1 * mu1;
    float y1 = fmaxf((v.y - mu1) * rsqrtf(var1 + EPS) * __ldg(g2 + c1) + __ldg(b2 + c1), 0.f);
    ((float2*)d_out2)[(size_t)n * 32 + lane] = make_float2(y0, y1);
    float g = y0 * __ldg(Wg + c0) + y1 * __ldg(Wg + c1);
#pragma unroll
    for (int off = 16; off >= 1; off >>= 1)
        g += __shfl_xor_sync(0xFFFFFFFFu, g, off);
    if (lane == 0) d_gate[n] = g + bg[0];
}

// ------------------- pooling ------------------------------------------------------------
__device__ __forceinline__ int lbound(const int* a, int n, int v) {
    int lo = 0, hi = n;
    while (lo < hi) {
        int mid = (lo + hi) >> 1;
        if (a[mid] < v) lo = mid + 1; else hi = mid;
    }
    return lo;
}

__global__ void __launch_bounds__(64) pool_kernel(const int* __restrict__ batch,
                                                  float* __restrict__ out) {
    int b = blockIdx.x, t = threadIdx.x;
    __shared__ int slo, shi;
    __shared__ float red[64];
    __shared__ float sh_w[64];
    if (t == 0) { slo = lbound(batch, NN, b); shi = lbound(batch, NN, b + 1); }
    __syncthreads();
    int lo = slo, hi = shi;
    if (hi <= lo) { out[b * 64 + t] = 0.f; return; }
    float mx = -3.4e38f;
    for (int n = lo + t; n < hi; n += 64) mx = fmaxf(mx, d_gate[n]);
    red[t] = mx;
    __syncthreads();
    if (t == 0) {
        float m = red[0];
        for (int j = 1; j < 64; j++) m = fmaxf(m, red[j]);
        red[0] = m;
    }
    __syncthreads();
    float m = red[0];
    __syncthreads();
    float ts = 0.f;
    for (int n = lo + t; n < hi; n += 64) ts += expf(d_gate[n] - m);
    red[t] = ts;
    __syncthreads();
    if (t == 0) {
        float s = 0.f;
        for (int j = 0; j < 64; j++) s += red[j];
        red[0] = s;
    }
    __syncthreads();
    float sinv = 1.0f / red[0];
    float acc = 0.f;
    for (int base = lo; base < hi; base += 64) {
        int mcnt = min(64, hi - base);
        __syncthreads();
        if (t < mcnt) sh_w[t] = expf(d_gate[base + t] - m);
        __syncthreads();
        for (int j = 0; j < mcnt; j++)
            acc += sh_w[j] * d_out2[(size_t)(base + j) * 64 + t];
    }
    out[b * 64 + t] = acc * sinv;
}

// ------------------- launch ----------------------------------------------------------------
static inline int gdiv(long long a, int b) { return (int)((a + b - 1) / b); }

extern "C" void kernel_launch(void* const* d_in, const int* in_sizes, int n_in,
                              void* d_out, int out_size) {
    const float* x     = (const float*)d_in[0];
    const float* ea    = (const float*)d_in[1];
    const int*   ei    = (const int*)d_in[2];
    const int*   batch = (const int*)d_in[3];
    const float* W1    = (const float*)d_in[4];
    const float* We1   = (const float*)d_in[5];
    const float* as1   = (const float*)d_in[6];
    const float* ad1   = (const float*)d_in[7];
    const float* ae1   = (const float*)d_in[8];
    const float* b1    = (const float*)d_in[9];
    const float* g1    = (const float*)d_in[10];
    const float* bb1   = (const float*)d_in[11];
    const float* W2    = (const float*)d_in[12];
    const float* We2   = (const float*)d_in[13];
    const float* as2   = (const float*)d_in[14];
    const float* ad2   = (const float*)d_in[15];
    const float* ae2   = (const float*)d_in[16];
    const float* b2    = (const float*)d_in[17];
    const float* g2    = (const float*)d_in[18];
    const float* bb2   = (const float*)d_in[19];
    const float* Wg    = (const float*)d_in[20];
    const float* bg    = (const float*)d_in[21];
    float* out = (float*)d_out;

    const int* src = ei;
    const int* dst = ei + EE;

    float* p_tmp;  cudaGetSymbolAddress((void**)&p_tmp, d_tmp);
    float* p_out1; cudaGetSymbolAddress((void**)&p_out1, d_out1);
    float* p_xs2;  cudaGetSymbolAddress((void**)&p_xs2, d_xs2);

    init_all<<<gdiv(NN, 256), 256>>>();
    hist_kernel<<<gdiv(EE, 256), 256>>>(dst);
    scan_kernel<<<1, 1024>>>();
    csr_fill<<<gdiv(ET, 256), 256>>>(src, dst);
    prep<<<1, 512>>>(W1, as1, ad1, We1, ae1, We2, ae2);

    logits1<<<gdiv((long long)NN * 32, 256), 256>>>(x);
    edge_alpha1<<<gdiv(EE, 256), 256>>>(ea, src, dst);
    selfloop1<<<gdiv((long long)NN * 32, 256), 256>>>();
    gather1x<<<NN, 128>>>(x);
    {
        dim3 g(4, gdiv(NN, 128));
        gemm1_stats<<<g, 256>>>(p_tmp, W1, p_out1, b1);
    }
    {
        dim3 g(1, gdiv(NN, 128));
        gemm2_fused<<<g, 256>>>(p_out1, W2, p_xs2, g1, bb1, as2, ad2);
    }
    edge_alpha2<<<gdiv(ET, 256), 256>>>();
    gather2<<<NN, 128>>>(b2);
    bn_stats2<<<128, 64>>>();
    gate_bn<<<gdiv((long long)NN * 32, 256), 256>>>(g2, bb2, Wg, bg);
    pool_kernel<<<BB, 64>>>(batch, out);
}